// round 6
// baseline (speedup 1.0000x reference)
#include <cuda_runtime.h>
#include <cuda_fp16.h>
#include <cstdint>

// GraphConvNet: B=32, C=32, V=1024, L=13, support=3, order=2
// yt[i][m] = sum_v T[i][v] * X[m][v]; out = W * [x ; yt] + b  (fp16 tensor cores)
// T 1-term fp16 (A^2 computed with exact 2-term split), W exact 2-term split.

#define V_N   1024
#define MCOLS 13312
#define MI    6144
#define CIN   224
#define NB    32

// ---------------- scratch ----------------
__device__ float  g_Asq[3u * 1024u * 1024u];
__device__ __half g_yt [(size_t)MI * MCOLS];
__device__ __half g_Abf_h[(size_t)MI * V_N];
__device__ __half g_Abf_l[(size_t)MI * V_N];      // only rows [s*2048, s*2048+1024) used (mode0)
__device__ __half g_Bh [3u * 1024u * 1024u];
__device__ __half g_Xh [(size_t)MCOLS * V_N];
__device__ __half g_Wh [64 * CIN];
__device__ __half g_Wl [64 * CIN];

// ================= helpers =================
__device__ __forceinline__ uint32_t smem_u32(const void* p) {
    uint32_t a;
    asm("{ .reg .u64 t; cvta.to.shared.u64 t, %1; cvt.u32.u64 %0, t; }" : "=r"(a) : "l"(p));
    return a;
}
#define CP16(s, g) asm volatile("cp.async.cg.shared.global [%0], [%1], 16;" :: "r"(s), "l"(g))
#define CP_COMMIT() asm volatile("cp.async.commit_group;")
#define CP_WAIT2()  asm volatile("cp.async.wait_group 2;")
#define CP_WAIT0()  asm volatile("cp.async.wait_group 0;")

#define LDSM4(r, addr)                                                          \
    asm volatile("ldmatrix.sync.aligned.m8n8.x4.shared.b16 {%0,%1,%2,%3}, [%4];"\
        : "=r"((r)[0]), "=r"((r)[1]), "=r"((r)[2]), "=r"((r)[3]) : "r"(addr))

#define MMAH(d, a, b0, b1)                                                      \
    asm volatile("mma.sync.aligned.m16n8k16.row.col.f32.f16.f16.f32 "           \
        "{%0,%1,%2,%3},{%4,%5,%6,%7},{%8,%9},{%0,%1,%2,%3};"                    \
        : "+f"((d)[0]), "+f"((d)[1]), "+f"((d)[2]), "+f"((d)[3])                \
        : "r"((a)[0]), "r"((a)[1]), "r"((a)[2]), "r"((a)[3]), "r"(b0), "r"(b1))

// ---------------- staging converts ----------------
__global__ void k_convA_direct(const float* __restrict__ A0, const float* __restrict__ A1,
                               const float* __restrict__ A2) {
    int idx = blockIdx.x * 256 + threadIdx.x;
    if (idx >= 3 * 1024 * 1024) return;
    int s = idx >> 20;
    int rem = idx & 0xFFFFF;
    const float* A = (s == 0) ? A0 : ((s == 1) ? A1 : A2);
    g_Bh[idx] = __float2half(A[rem]);
}

__global__ void k_transposeA_conv(const float* __restrict__ A0, const float* __restrict__ A1,
                                  const float* __restrict__ A2) {
    __shared__ float t[32][33];
    int s = blockIdx.z;
    const float* A = (s == 0) ? A0 : ((s == 1) ? A1 : A2);
    int wb = blockIdx.x * 32, vb = blockIdx.y * 32;
#pragma unroll
    for (int j = 0; j < 32; j += 8)
        t[threadIdx.y + j][threadIdx.x] = A[(size_t)(vb + threadIdx.y + j) * 1024 + wb + threadIdx.x];
    __syncthreads();
#pragma unroll
    for (int j = 0; j < 32; j += 8) {
        float f = t[threadIdx.x][threadIdx.y + j];
        __half h = __float2half(f);
        size_t o = (size_t)(s * 2048 + wb + threadIdx.y + j) * 1024 + vb + threadIdx.x;
        g_Abf_h[o] = h;
        g_Abf_l[o] = __float2half(f - __half2float(h));
    }
}

__global__ void k_conv_sq() {
    int idx = blockIdx.x * 256 + threadIdx.x;
    if (idx >= 3 * 1024 * 1024) return;
    int s = idx >> 20;
    int rem = idx & 0xFFFFF;
    int w = rem >> 10, v = rem & 1023;
    g_Abf_h[(size_t)(s * 2048 + 1024 + w) * 1024 + v] = __float2half(g_Asq[idx]);
}

__global__ void k_convX(const float* __restrict__ x) {
    __shared__ float s[512 * 13];
    int bc = blockIdx.x >> 1;
    int vh = blockIdx.x & 1;
    const float* src = x + (size_t)bc * MCOLS + vh * 6656;
    for (int e = threadIdx.x; e < 6656; e += 256) s[e] = src[e];
    __syncthreads();
    for (int e = threadIdx.x; e < 6656; e += 256) {
        int l = e >> 9;
        int vloc = e & 511;
        g_Xh[(size_t)(bc * 13 + l) * 1024 + vh * 512 + vloc] = __float2half(s[vloc * 13 + l]);
    }
}

__global__ void k_convW(const float* __restrict__ W) {
    int idx = blockIdx.x * 256 + threadIdx.x;
    if (idx >= 64 * CIN) return;
    float f = W[idx];
    __half h = __float2half(f);
    g_Wh[idx] = h;
    g_Wl[idx] = __float2half(f - __half2float(h));
}

// ---------------- main GEMM ----------------
// BM=128, BN=256, BK=64, 3-stage, 256 thr, warp 64x64.
// mode 0: (A^T)^2 with 2-term A split -> g_Asq fp32
// mode 1: diffusion, 1-term -> g_yt fp16
#define STAGE_B0 65536          // Ah 16K | Al 16K | Xh 32K
#define STAGE_B1 49152          // Ah 16K | Xh 32K
#define GEMM_DYN0 (3 * STAGE_B0)
#define GEMM_DYN1 (3 * STAGE_B1)

__global__ __launch_bounds__(256, 1) void k_gemm(int mode) {
    extern __shared__ char sm[];
    const uint32_t sbase = smem_u32(sm);
    const int tid = threadIdx.x, lane = tid & 31, wid = tid >> 5;

    const __half *Ah, *Al, *Bh;
    if (mode == 0) {
        int s = blockIdx.z;
        Ah = g_Abf_h + (size_t)(s * 2048) * 1024;
        Al = g_Abf_l + (size_t)(s * 2048) * 1024;
        Bh = g_Bh + ((size_t)s << 20);
    } else {
        Ah = g_Abf_h; Al = g_Abf_h; Bh = g_Xh;
    }
    const uint32_t stageB = (mode == 0) ? STAGE_B0 : STAGE_B1;
    const uint32_t xoff   = (mode == 0) ? 32768u : 16384u;
    const size_t i0 = (size_t)blockIdx.x * 128;
    const size_t j0 = (size_t)blockIdx.y * 256;

    const int wm = (wid & 1) * 64;
    const int wn = (wid >> 1) * 64;
    const int arow = wm + (lane & 15);
    const int a_x7 = arow & 7;
    const int a_cs = lane >> 4;
    const int brow = wn + ((lane >> 4) << 3) + (lane & 7);
    const int b_x7 = brow & 7;
    const int b_cs = (lane >> 3) & 1;

    float acc[4][8][4];
#pragma unroll
    for (int mt = 0; mt < 4; mt++)
#pragma unroll
        for (int nt = 0; nt < 8; nt++)
#pragma unroll
            for (int q = 0; q < 4; q++) acc[mt][nt][q] = 0.f;

    auto load_stage = [&](int st, int buf) {
        const int kv0 = st * 64;
        const uint32_t sb = sbase + buf * stageB;
#pragma unroll
        for (int q = 0; q < 4; q++) {
            int id = tid + 256 * q;
            int row = id >> 3, kc = id & 7;
            uint32_t sw = row * 128 + ((kc ^ (row & 7)) << 4);
            size_t go = (i0 + row) * 1024 + kv0 + kc * 8;
            CP16(sb + sw, Ah + go);
            if (mode == 0) CP16(sb + 16384 + sw, Al + go);
        }
#pragma unroll
        for (int q = 0; q < 8; q++) {
            int id = tid + 256 * q;
            int row = id >> 3, kc = id & 7;
            uint32_t sw = row * 128 + ((kc ^ (row & 7)) << 4);
            CP16(sb + xoff + sw, Bh + (j0 + row) * 1024 + kv0 + kc * 8);
        }
    };

    load_stage(0, 0); CP_COMMIT();
    load_stage(1, 1); CP_COMMIT();
    load_stage(2, 2); CP_COMMIT();

    int buf = 0;
    for (int st = 0; st < 16; ++st) {
        CP_WAIT2();
        __syncthreads();
        const uint32_t sb = sbase + buf * stageB;
#pragma unroll
        for (int kk = 0; kk < 4; kk++) {
            uint32_t ah[4][4], al[4][4];
#pragma unroll
            for (int mt = 0; mt < 4; mt++) {
                uint32_t addr = sb + (arow + mt * 16) * 128 + (((kk * 2 + a_cs) ^ a_x7) << 4);
                LDSM4(ah[mt], addr);
                if (mode == 0) LDSM4(al[mt], addr + 16384);
            }
#pragma unroll
            for (int nt2 = 0; nt2 < 4; nt2++) {
                uint32_t bh[4];
                LDSM4(bh, sb + xoff + (brow + nt2 * 16) * 128 +
                          (((kk * 2 + b_cs) ^ b_x7) << 4));
#pragma unroll
                for (int mt = 0; mt < 4; mt++) {
                    MMAH(acc[mt][nt2 * 2],     ah[mt], bh[0], bh[1]);
                    MMAH(acc[mt][nt2 * 2 + 1], ah[mt], bh[2], bh[3]);
                    if (mode == 0) {
                        MMAH(acc[mt][nt2 * 2],     al[mt], bh[0], bh[1]);
                        MMAH(acc[mt][nt2 * 2 + 1], al[mt], bh[2], bh[3]);
                    }
                }
            }
        }
        __syncthreads();
        if (st + 3 < 16) load_stage(st + 3, buf);
        CP_COMMIT();
        buf = (buf + 1 == 3) ? 0 : buf + 1;
    }

    const int crow = lane >> 2;
    const int ccol = (lane & 3) * 2;
    if (mode == 0) {
        float* C = g_Asq + ((size_t)blockIdx.z << 20);
#pragma unroll
        for (int mt = 0; mt < 4; mt++) {
            size_t rbase = (i0 + wm + mt * 16 + crow) * 1024 + j0 + wn + ccol;
#pragma unroll
            for (int nt = 0; nt < 8; nt++) {
                float* p = C + rbase + nt * 8;
                *(float2*)p              = make_float2(acc[mt][nt][0], acc[mt][nt][1]);
                *(float2*)(p + 8 * 1024) = make_float2(acc[mt][nt][2], acc[mt][nt][3]);
            }
        }
    } else {
#pragma unroll
        for (int mt = 0; mt < 4; mt++) {
            size_t rbase = (i0 + wm + mt * 16 + crow) * MCOLS + j0 + wn + ccol;
#pragma unroll
            for (int nt = 0; nt < 8; nt++) {
                __half* p = g_yt + rbase + nt * 8;
                *(__half2*)p               = __floats2half2_rn(acc[mt][nt][0], acc[mt][nt][1]);
                *(__half2*)(p + 8 * MCOLS) = __floats2half2_rn(acc[mt][nt][2], acc[mt][nt][3]);
            }
        }
    }
}

// ---------------- fused final: gather yt/x -> smem H tile -> MMA ----------------
// grid (104 n-tiles, 32 b); M=64, N=128, K=224.
#define F_SYT 0                              // [6][11][416] halves
#define F_SX  (6 * 11 * 416 * 2)             // 54912 ; [32][146] halves
#define F_HS  (F_SX + 32 * 146 * 2)          // 64256 ; [128] pitch 464B
#define F_WH  (F_HS + 128 * 464)             // 123648
#define F_WL  (F_WH + 64 * 464)              // 153344
#define F_DYN (F_WL + 64 * 464)              // 183040

__global__ __launch_bounds__(256, 1) void k_final(const float* __restrict__ x,
                                                  const float* __restrict__ bias,
                                                  float* __restrict__ out) {
    extern __shared__ char sm[];
    const uint32_t sbase = smem_u32(sm);
    __half* s_half = (__half*)sm;
    const int tid = threadIdx.x, lane = tid & 31, wid = tid >> 5;
    const int b = blockIdx.y;
    const int j0 = blockIdx.x * 128;
    const int v0 = j0 / 13;

    // stage W split (cp.async)
    for (int e = tid; e < 64 * 28; e += 256) {
        int r = e / 28, q = e - r * 28;
        CP16(sbase + F_WH + r * 464 + q * 16, g_Wh + r * CIN + q * 8);
        CP16(sbase + F_WL + r * 464 + q * 16, g_Wl + r * CIN + q * 8);
    }
    // stage yt slice: 6 g x 11 v rows, 416 halves each
    for (int e = tid; e < 66 * 52; e += 256) {
        int row = e / 52, q = e - row * 52;
        int g = row / 11, vi = row - g * 11;
        int v = v0 + vi;
        if (v < 1024)
            CP16(sbase + F_SYT + (row * 416 + q * 8) * 2,
                 g_yt + ((size_t)(g * 1024 + v)) * MCOLS + b * 416 + q * 8);
    }
    CP_COMMIT();
    // stage x slice with fp16 convert: [32 c][143 cols], pitch 146
    {
        const float* xb = x + (size_t)b * 32 * MCOLS + v0 * 13;
        int lim = MCOLS - v0 * 13;
        for (int e2 = tid; e2 < 32 * 143; e2 += 256) {
            int c = e2 / 143, e = e2 - c * 143;
            float f = (e < lim) ? xb[(size_t)c * MCOLS + e] : 0.f;
            s_half[F_SX / 2 + c * 146 + e] = __float2half(f);
        }
    }
    CP_WAIT0();
    __syncthreads();

    // build H tile [128 rows][224 ct], pitch 464B
    for (int e = tid; e < 128 * 28; e += 256) {
        int r = e / 28, q = e - r * 28;
        int nn = j0 + r;
        int v = nn / 13, l = nn - v * 13, vi = v - v0;
        union { uint4 u; __half2 h[4]; } pk;
        if (q < 4) {
            const __half* sx = s_half + F_SX / 2 + vi * 13 + l;
            int c0 = q * 8;
#pragma unroll
            for (int i = 0; i < 4; i++)
                pk.h[i] = __halves2half2(sx[(c0 + 2 * i) * 146], sx[(c0 + 2 * i + 1) * 146]);
        } else {
            int ct0 = q * 8;
            int g = ct0 >> 5, c0 = ct0 & 31;
            const __half* row = s_half + ((g - 1) * 11 + vi) * 416 + l;
#pragma unroll
            for (int i = 0; i < 4; i++)
                pk.h[i] = __halves2half2(row[(c0 + 2 * i) * 13], row[(c0 + 2 * i + 1) * 13]);
        }
        *(uint4*)(sm + F_HS + r * 464 + q * 16) = pk.u;
    }
    __syncthreads();

    const int wm = (wid & 1) * 32;
    const int wn = (wid >> 1) * 32;
    const int arow_l = lane & 15;
    const int a_cs = lane >> 4;
    const int brow_l = ((lane >> 4) << 3) + (lane & 7);
    const int b_cs = (lane >> 3) & 1;

    float acc[2][4][4];
#pragma unroll
    for (int mt = 0; mt < 2; mt++)
#pragma unroll
        for (int nt = 0; nt < 4; nt++)
#pragma unroll
            for (int q = 0; q < 4; q++) acc[mt][nt][q] = 0.f;

#pragma unroll
    for (int kc = 0; kc < 14; kc++) {
        uint32_t wh[2][4], wl[2][4];
#pragma unroll
        for (int mt = 0; mt < 2; mt++) {
            uint32_t ao = (wm + mt * 16 + arow_l) * 464 + (kc * 2 + a_cs) * 16;
            LDSM4(wh[mt], sbase + F_WH + ao);
            LDSM4(wl[mt], sbase + F_WL + ao);
        }
#pragma unroll
        for (int nt2 = 0; nt2 < 2; nt2++) {
            uint32_t bh[4];
            LDSM4(bh, sbase + F_HS + (wn + nt2 * 16 + brow_l) * 464 +
                      (kc * 2 + b_cs) * 16);
#pragma unroll
            for (int mt = 0; mt < 2; mt++) {
                MMAH(acc[mt][nt2 * 2],     wh[mt], bh[0], bh[1]);
                MMAH(acc[mt][nt2 * 2],     wl[mt], bh[0], bh[1]);
                MMAH(acc[mt][nt2 * 2 + 1], wh[mt], bh[2], bh[3]);
                MMAH(acc[mt][nt2 * 2 + 1], wl[mt], bh[2], bh[3]);
            }
        }
    }

    const int crow = lane >> 2;
    const int ccol = (lane & 3) * 2;
#pragma unroll
    for (int mt = 0; mt < 2; mt++) {
        int o = wm + mt * 16 + crow;
        float b0 = bias[o], b1 = bias[o + 8];
        size_t r0 = (size_t)(b * 64 + o) * MCOLS + j0 + wn + ccol;
#pragma unroll
        for (int nt = 0; nt < 4; nt++) {
            float* p = out + r0 + nt * 8;
            *(float2*)p               = make_float2(acc[mt][nt][0] + b0, acc[mt][nt][1] + b0);
            *(float2*)(p + 8 * MCOLS) = make_float2(acc[mt][nt][2] + b1, acc[mt][nt][3] + b1);
        }
    }
}

// ---------------- launcher ----------------
extern "C" void kernel_launch(void* const* d_in, const int* in_sizes, int n_in,
                              void* d_out, int out_size) {
    const float* x    = (const float*)d_in[0];
    const float* A0   = (const float*)d_in[1];
    const float* A1   = (const float*)d_in[2];
    const float* A2   = (const float*)d_in[3];
    const float* W    = (const float*)d_in[4];
    const float* bias = (const float*)d_in[5];
    float* out = (float*)d_out;

    cudaFuncSetAttribute(k_gemm, cudaFuncAttributeMaxDynamicSharedMemorySize, GEMM_DYN0);
    cudaFuncSetAttribute(k_final, cudaFuncAttributeMaxDynamicSharedMemorySize, F_DYN);

    k_convA_direct<<<(3 * 1024 * 1024 + 255) / 256, 256>>>(A0, A1, A2);
    k_transposeA_conv<<<dim3(32, 32, 3), dim3(32, 8)>>>(A0, A1, A2);
    k_convX<<<2048, 256>>>(x);
    k_convW<<<56, 256>>>(W);

    k_gemm<<<dim3(8, 4, 3), 256, GEMM_DYN0>>>(0);    // (A^T)^2, exact split
    k_conv_sq<<<(3 * 1024 * 1024 + 255) / 256, 256>>>();

    k_gemm<<<dim3(48, 52, 1), 256, GEMM_DYN1>>>(1);  // diffusion, 1-term -> g_yt

    k_final<<<dim3(104, 32), 256, F_DYN>>>(x, bias, out);
}

// round 7
// speedup vs baseline: 1.0794x; 1.0794x over previous
#include <cuda_runtime.h>
#include <cuda_fp16.h>
#include <cstdint>

// GraphConvNet: B=32, C=32, V=1024, L=13, support=3, order=2
// yt[i][m] = sum_v T[i][v] * X[m][v]; out = W * [x ; yt] + b  (fp16 tensor cores)
// Diffusion GEMM 1-term fp16 (accuracy-validated R6); A^2 exact 2-term; W exact 2-term.

#define V_N   1024
#define MCOLS 13312
#define MI    6144
#define CIN   224
#define NB    32
#define PAD_E 232

// ---------------- scratch ----------------
__device__ float  g_Asq[3u * 1024u * 1024u];
__device__ __half g_yt [(size_t)MI * MCOLS];
__device__ __half g_Abf_h[(size_t)MI * V_N];
__device__ __half g_Abf_l[(size_t)MI * V_N];      // only rows [s*2048, s*2048+1024) used (mode0)
__device__ __half g_Bh [3u * 1024u * 1024u];
__device__ __half g_Xh [(size_t)MCOLS * V_N];
__device__ __half g_Hf [(size_t)NB * MCOLS * CIN];
__device__ __half g_Wh [64 * CIN];
__device__ __half g_Wl [64 * CIN];

// ================= helpers =================
__device__ __forceinline__ uint32_t smem_u32(const void* p) {
    uint32_t a;
    asm("{ .reg .u64 t; cvta.to.shared.u64 t, %1; cvt.u32.u64 %0, t; }" : "=r"(a) : "l"(p));
    return a;
}
#define CP16(s, g) asm volatile("cp.async.cg.shared.global [%0], [%1], 16;" :: "r"(s), "l"(g))
#define CP_COMMIT() asm volatile("cp.async.commit_group;")
#define CP_WAIT2()  asm volatile("cp.async.wait_group 2;")
#define CP_WAIT0()  asm volatile("cp.async.wait_group 0;")

#define LDSM4(r, addr)                                                          \
    asm volatile("ldmatrix.sync.aligned.m8n8.x4.shared.b16 {%0,%1,%2,%3}, [%4];"\
        : "=r"((r)[0]), "=r"((r)[1]), "=r"((r)[2]), "=r"((r)[3]) : "r"(addr))

#define MMAH(d, a, b0, b1)                                                      \
    asm volatile("mma.sync.aligned.m16n8k16.row.col.f32.f16.f16.f32 "           \
        "{%0,%1,%2,%3},{%4,%5,%6,%7},{%8,%9},{%0,%1,%2,%3};"                    \
        : "+f"((d)[0]), "+f"((d)[1]), "+f"((d)[2]), "+f"((d)[3])                \
        : "r"((a)[0]), "r"((a)[1]), "r"((a)[2]), "r"((a)[3]), "r"(b0), "r"(b1))

// ---------------- staging converts ----------------
__global__ void k_convA_direct(const float* __restrict__ A0, const float* __restrict__ A1,
                               const float* __restrict__ A2) {
    int idx = blockIdx.x * 256 + threadIdx.x;
    if (idx >= 3 * 1024 * 1024) return;
    int s = idx >> 20;
    int rem = idx & 0xFFFFF;
    const float* A = (s == 0) ? A0 : ((s == 1) ? A1 : A2);
    g_Bh[idx] = __float2half(A[rem]);
}

__global__ void k_transposeA_conv(const float* __restrict__ A0, const float* __restrict__ A1,
                                  const float* __restrict__ A2) {
    __shared__ float t[32][33];
    int s = blockIdx.z;
    const float* A = (s == 0) ? A0 : ((s == 1) ? A1 : A2);
    int wb = blockIdx.x * 32, vb = blockIdx.y * 32;
#pragma unroll
    for (int j = 0; j < 32; j += 8)
        t[threadIdx.y + j][threadIdx.x] = A[(size_t)(vb + threadIdx.y + j) * 1024 + wb + threadIdx.x];
    __syncthreads();
#pragma unroll
    for (int j = 0; j < 32; j += 8) {
        float f = t[threadIdx.x][threadIdx.y + j];
        __half h = __float2half(f);
        size_t o = (size_t)(s * 2048 + wb + threadIdx.y + j) * 1024 + vb + threadIdx.x;
        g_Abf_h[o] = h;
        g_Abf_l[o] = __float2half(f - __half2float(h));
    }
}

__global__ void k_conv_sq() {
    int idx = blockIdx.x * 256 + threadIdx.x;
    if (idx >= 3 * 1024 * 1024) return;
    int s = idx >> 20;
    int rem = idx & 0xFFFFF;
    int w = rem >> 10, v = rem & 1023;
    g_Abf_h[(size_t)(s * 2048 + 1024 + w) * 1024 + v] = __float2half(g_Asq[idx]);
}

__global__ void k_convX(const float* __restrict__ x) {
    __shared__ float s[512 * 13];
    int bc = blockIdx.x >> 1;
    int vh = blockIdx.x & 1;
    const float* src = x + (size_t)bc * MCOLS + vh * 6656;
    for (int e = threadIdx.x; e < 6656; e += 256) s[e] = src[e];
    __syncthreads();
    for (int e = threadIdx.x; e < 6656; e += 256) {
        int l = e >> 9;
        int vloc = e & 511;
        g_Xh[(size_t)(bc * 13 + l) * 1024 + vh * 512 + vloc] = __float2half(s[vloc * 13 + l]);
    }
}

__global__ void k_convW(const float* __restrict__ W) {
    int idx = blockIdx.x * 256 + threadIdx.x;
    if (idx >= 64 * CIN) return;
    float f = W[idx];
    __half h = __float2half(f);
    g_Wh[idx] = h;
    g_Wl[idx] = __float2half(f - __half2float(h));
}

// ---------------- main GEMM ----------------
// BM=128, BN=256, BK=64, 3-stage, 256 thr, warp 64x64.
// mode 0: (A^T)^2 with 2-term A split -> g_Asq fp32
// mode 1: diffusion, 1-term -> g_yt fp16
#define STAGE_B0 65536          // Ah 16K | Al 16K | Xh 32K
#define STAGE_B1 49152          // Ah 16K | Xh 32K
#define GEMM_DYN0 (3 * STAGE_B0)
#define GEMM_DYN1 (3 * STAGE_B1)

__global__ __launch_bounds__(256, 1) void k_gemm(int mode) {
    extern __shared__ char sm[];
    const uint32_t sbase = smem_u32(sm);
    const int tid = threadIdx.x, lane = tid & 31, wid = tid >> 5;

    const __half *Ah, *Al, *Bh;
    if (mode == 0) {
        int s = blockIdx.z;
        Ah = g_Abf_h + (size_t)(s * 2048) * 1024;
        Al = g_Abf_l + (size_t)(s * 2048) * 1024;
        Bh = g_Bh + ((size_t)s << 20);
    } else {
        Ah = g_Abf_h; Al = g_Abf_h; Bh = g_Xh;
    }
    const uint32_t stageB = (mode == 0) ? STAGE_B0 : STAGE_B1;
    const uint32_t xoff   = (mode == 0) ? 32768u : 16384u;
    const size_t i0 = (size_t)blockIdx.x * 128;
    const size_t j0 = (size_t)blockIdx.y * 256;

    const int wm = (wid & 1) * 64;
    const int wn = (wid >> 1) * 64;
    const int arow = wm + (lane & 15);
    const int a_x7 = arow & 7;
    const int a_cs = lane >> 4;
    const int brow = wn + ((lane >> 4) << 3) + (lane & 7);
    const int b_x7 = brow & 7;
    const int b_cs = (lane >> 3) & 1;

    float acc[4][8][4];
#pragma unroll
    for (int mt = 0; mt < 4; mt++)
#pragma unroll
        for (int nt = 0; nt < 8; nt++)
#pragma unroll
            for (int q = 0; q < 4; q++) acc[mt][nt][q] = 0.f;

    auto load_stage = [&](int st, int buf) {
        const int kv0 = st * 64;
        const uint32_t sb = sbase + buf * stageB;
#pragma unroll
        for (int q = 0; q < 4; q++) {
            int id = tid + 256 * q;
            int row = id >> 3, kc = id & 7;
            uint32_t sw = row * 128 + ((kc ^ (row & 7)) << 4);
            size_t go = (i0 + row) * 1024 + kv0 + kc * 8;
            CP16(sb + sw, Ah + go);
            if (mode == 0) CP16(sb + 16384 + sw, Al + go);
        }
#pragma unroll
        for (int q = 0; q < 8; q++) {
            int id = tid + 256 * q;
            int row = id >> 3, kc = id & 7;
            uint32_t sw = row * 128 + ((kc ^ (row & 7)) << 4);
            CP16(sb + xoff + sw, Bh + (j0 + row) * 1024 + kv0 + kc * 8);
        }
    };

    load_stage(0, 0); CP_COMMIT();
    load_stage(1, 1); CP_COMMIT();
    load_stage(2, 2); CP_COMMIT();

    int buf = 0;
    for (int st = 0; st < 16; ++st) {
        CP_WAIT2();
        __syncthreads();
        const uint32_t sb = sbase + buf * stageB;
#pragma unroll
        for (int kk = 0; kk < 4; kk++) {
            uint32_t ah[4][4], al[4][4];
#pragma unroll
            for (int mt = 0; mt < 4; mt++) {
                uint32_t addr = sb + (arow + mt * 16) * 128 + (((kk * 2 + a_cs) ^ a_x7) << 4);
                LDSM4(ah[mt], addr);
                if (mode == 0) LDSM4(al[mt], addr + 16384);
            }
#pragma unroll
            for (int nt2 = 0; nt2 < 4; nt2++) {
                uint32_t bh[4];
                LDSM4(bh, sb + xoff + (brow + nt2 * 16) * 128 +
                          (((kk * 2 + b_cs) ^ b_x7) << 4));
#pragma unroll
                for (int mt = 0; mt < 4; mt++) {
                    MMAH(acc[mt][nt2 * 2],     ah[mt], bh[0], bh[1]);
                    MMAH(acc[mt][nt2 * 2 + 1], ah[mt], bh[2], bh[3]);
                    if (mode == 0) {
                        MMAH(acc[mt][nt2 * 2],     al[mt], bh[0], bh[1]);
                        MMAH(acc[mt][nt2 * 2 + 1], al[mt], bh[2], bh[3]);
                    }
                }
            }
        }
        __syncthreads();
        if (st + 3 < 16) load_stage(st + 3, buf);
        CP_COMMIT();
        buf = (buf + 1 == 3) ? 0 : buf + 1;
    }

    const int crow = lane >> 2;
    const int ccol = (lane & 3) * 2;
    if (mode == 0) {
        float* C = g_Asq + ((size_t)blockIdx.z << 20);
#pragma unroll
        for (int mt = 0; mt < 4; mt++) {
            size_t rbase = (i0 + wm + mt * 16 + crow) * 1024 + j0 + wn + ccol;
#pragma unroll
            for (int nt = 0; nt < 8; nt++) {
                float* p = C + rbase + nt * 8;
                *(float2*)p              = make_float2(acc[mt][nt][0], acc[mt][nt][1]);
                *(float2*)(p + 8 * 1024) = make_float2(acc[mt][nt][2], acc[mt][nt][3]);
            }
        }
    } else {
#pragma unroll
        for (int mt = 0; mt < 4; mt++) {
            size_t rbase = (i0 + wm + mt * 16 + crow) * MCOLS + j0 + wn + ccol;
#pragma unroll
            for (int nt = 0; nt < 8; nt++) {
                __half* p = g_yt + rbase + nt * 8;
                *(__half2*)p               = __floats2half2_rn(acc[mt][nt][0], acc[mt][nt][1]);
                *(__half2*)(p + 8 * MCOLS) = __floats2half2_rn(acc[mt][nt][2], acc[mt][nt][3]);
            }
        }
    }
}

// ---------------- transpose/pack: Hf[(b,v,l)][ct] from x + g_yt ----------------
#define TRANS_DYN (48 * 416 * 2 + 32 * 104 * 4)

__global__ __launch_bounds__(256) void k_trans(const float* __restrict__ x) {
    extern __shared__ char sm[];
    __half* syt = (__half*)sm;                 // [48][416]
    float*  sx  = (float*)(sm + 48 * 416 * 2); // [32][104]
    const int v0 = blockIdx.x * 8;
    const int b  = blockIdx.y;
    const int tid = threadIdx.x;

    for (int e = tid; e < 48 * 52; e += 256) {
        int r = e / 52, q = e - r * 52;
        int g = r >> 3, vi = r & 7;
        const __half* src = g_yt + ((size_t)(g * 1024 + v0 + vi)) * MCOLS + b * 416 + q * 8;
        *(uint4*)(syt + r * 416 + q * 8) = *(const uint4*)src;
    }
    for (int e = tid; e < 32 * 26; e += 256) {
        int c = e / 26, q = e - c * 26;
        const float* src = x + (size_t)(b * 32 + c) * MCOLS + v0 * 13 + q * 4;
        *(float4*)(sx + c * 104 + q * 4) = *(const float4*)src;
    }
    __syncthreads();

    for (int e = tid; e < 104 * 28; e += 256) {
        int n = e / 28, q = e - n * 28;
        int vi = n / 13, l = n - vi * 13;
        int ct0 = q * 8;
        union { uint4 u; __half2 h[4]; } pk;
        if (q < 4) {
            int c0 = ct0;
#pragma unroll
            for (int i = 0; i < 4; i++)
                pk.h[i] = __floats2half2_rn(sx[(c0 + 2 * i) * 104 + n],
                                            sx[(c0 + 2 * i + 1) * 104 + n]);
        } else {
            int g = ct0 >> 5, c0 = ct0 & 31;
            const __half* row = syt + ((g - 1) * 8 + vi) * 416 + l;
#pragma unroll
            for (int i = 0; i < 4; i++)
                pk.h[i] = __halves2half2(row[(c0 + 2 * i) * 13], row[(c0 + 2 * i + 1) * 13]);
        }
        *(uint4*)(g_Hf + ((size_t)(b * MCOLS + v0 * 13 + n)) * CIN + ct0) = pk.u;
    }
}

// ---------------- final MMA: out[(b,o)][n] = (Wh+Wl) * Hf + bias ----------------
#define FIN_WH   0
#define FIN_WL   (64 * PAD_E * 2)
#define FIN_HS   (128 * PAD_E * 2)
#define FIN_DYN  (FIN_WL + FIN_HS + 128 * PAD_E * 2)

__global__ __launch_bounds__(256, 1) void k_final(const float* __restrict__ bias,
                                                  float* __restrict__ out) {
    extern __shared__ char sm[];
    const uint32_t sbase = smem_u32(sm);
    const int tid = threadIdx.x, lane = tid & 31, wid = tid >> 5;
    const int b = blockIdx.y;
    const int j0 = blockIdx.x * 128;

    for (int e = tid; e < 64 * 28; e += 256) {
        int r = e / 28, q = e - r * 28;
        CP16(sbase + FIN_WH + r * 464 + q * 16, g_Wh + r * CIN + q * 8);
        CP16(sbase + FIN_WL + r * 464 + q * 16, g_Wl + r * CIN + q * 8);
    }
    for (int e = tid; e < 128 * 28; e += 256) {
        int r = e / 28, q = e - r * 28;
        CP16(sbase + FIN_HS + r * 464 + q * 16,
             g_Hf + ((size_t)(b * MCOLS + j0 + r)) * CIN + q * 8);
    }
    CP_COMMIT();
    CP_WAIT0();
    __syncthreads();

    const int wm = (wid & 1) * 32;
    const int wn = (wid >> 1) * 32;
    const int arow_l = lane & 15;
    const int a_cs = lane >> 4;
    const int brow_l = ((lane >> 4) << 3) + (lane & 7);
    const int b_cs = (lane >> 3) & 1;

    float acc[2][4][4];
#pragma unroll
    for (int mt = 0; mt < 2; mt++)
#pragma unroll
        for (int nt = 0; nt < 4; nt++)
#pragma unroll
            for (int q = 0; q < 4; q++) acc[mt][nt][q] = 0.f;

#pragma unroll
    for (int kc = 0; kc < 14; kc++) {
        uint32_t wh[2][4], wl[2][4];
#pragma unroll
        for (int mt = 0; mt < 2; mt++) {
            uint32_t ao = (wm + mt * 16 + arow_l) * 464 + (kc * 2 + a_cs) * 16;
            LDSM4(wh[mt], sbase + FIN_WH + ao);
            LDSM4(wl[mt], sbase + FIN_WL + ao);
        }
#pragma unroll
        for (int nt2 = 0; nt2 < 2; nt2++) {
            uint32_t bh[4];
            LDSM4(bh, sbase + FIN_HS + (wn + nt2 * 16 + brow_l) * 464 +
                      (kc * 2 + b_cs) * 16);
#pragma unroll
            for (int mt = 0; mt < 2; mt++) {
                MMAH(acc[mt][nt2 * 2],     wh[mt], bh[0], bh[1]);
                MMAH(acc[mt][nt2 * 2],     wl[mt], bh[0], bh[1]);
                MMAH(acc[mt][nt2 * 2 + 1], wh[mt], bh[2], bh[3]);
                MMAH(acc[mt][nt2 * 2 + 1], wl[mt], bh[2], bh[3]);
            }
        }
    }

    const int crow = lane >> 2;
    const int ccol = (lane & 3) * 2;
#pragma unroll
    for (int mt = 0; mt < 2; mt++) {
        int o = wm + mt * 16 + crow;
        float b0 = bias[o], b1 = bias[o + 8];
        size_t r0 = (size_t)(b * 64 + o) * MCOLS + j0 + wn + ccol;
#pragma unroll
        for (int nt = 0; nt < 4; nt++) {
            float* p = out + r0 + nt * 8;
            *(float2*)p               = make_float2(acc[mt][nt][0] + b0, acc[mt][nt][1] + b0);
            *(float2*)(p + 8 * MCOLS) = make_float2(acc[mt][nt][2] + b1, acc[mt][nt][3] + b1);
        }
    }
}

// ---------------- launcher ----------------
extern "C" void kernel_launch(void* const* d_in, const int* in_sizes, int n_in,
                              void* d_out, int out_size) {
    const float* x    = (const float*)d_in[0];
    const float* A0   = (const float*)d_in[1];
    const float* A1   = (const float*)d_in[2];
    const float* A2   = (const float*)d_in[3];
    const float* W    = (const float*)d_in[4];
    const float* bias = (const float*)d_in[5];
    float* out = (float*)d_out;

    cudaFuncSetAttribute(k_gemm, cudaFuncAttributeMaxDynamicSharedMemorySize, GEMM_DYN0);
    cudaFuncSetAttribute(k_trans, cudaFuncAttributeMaxDynamicSharedMemorySize, TRANS_DYN);
    cudaFuncSetAttribute(k_final, cudaFuncAttributeMaxDynamicSharedMemorySize, FIN_DYN);

    k_convA_direct<<<(3 * 1024 * 1024 + 255) / 256, 256>>>(A0, A1, A2);
    k_transposeA_conv<<<dim3(32, 32, 3), dim3(32, 8)>>>(A0, A1, A2);
    k_convX<<<2048, 256>>>(x);
    k_convW<<<56, 256>>>(W);

    k_gemm<<<dim3(8, 4, 3), 256, GEMM_DYN0>>>(0);    // (A^T)^2, exact split
    k_conv_sq<<<(3 * 1024 * 1024 + 255) / 256, 256>>>();

    k_gemm<<<dim3(48, 52, 1), 256, GEMM_DYN1>>>(1);  // diffusion, 1-term -> g_yt

    k_trans<<<dim3(128, 32), 256, TRANS_DYN>>>(x);   // pack Hf
    k_final<<<dim3(104, 32), 256, FIN_DYN>>>(bias, out);
}

// round 8
// speedup vs baseline: 1.6626x; 1.5403x over previous
#include <cuda_runtime.h>
#include <cuda_fp16.h>
#include <cstdint>

// GraphConvNet: B=32, C=32, V=1024, L=13, support=3, order=2
// yt[i][m] = sum_v T[i][v] * X[m][v]; out = W * [x ; yt] + b  (fp16 tensor cores)
// gemm1 1-term fp16, 2 CTAs/SM; A^2 exact 2-term; W 1-term fp16.

#define V_N   1024
#define MCOLS 13312
#define MI    6144
#define CIN   224
#define NB    32
#define PAD_E 232

// ---------------- scratch ----------------
__device__ float  g_Asq[3u * 1024u * 1024u];
__device__ __half g_yt [(size_t)MI * MCOLS];
__device__ __half g_Abf_h[(size_t)MI * V_N];
__device__ __half g_Abf_l[(size_t)MI * V_N];
__device__ __half g_Bh [3u * 1024u * 1024u];
__device__ __half g_Xh [(size_t)MCOLS * V_N];
__device__ __half g_Hf [(size_t)NB * MCOLS * CIN];
__device__ __half g_Wh [64 * CIN];

// ================= helpers =================
__device__ __forceinline__ uint32_t smem_u32(const void* p) {
    uint32_t a;
    asm("{ .reg .u64 t; cvta.to.shared.u64 t, %1; cvt.u32.u64 %0, t; }" : "=r"(a) : "l"(p));
    return a;
}
#define CP16(s, g) asm volatile("cp.async.cg.shared.global [%0], [%1], 16;" :: "r"(s), "l"(g))
#define CP_COMMIT() asm volatile("cp.async.commit_group;")
#define CP_WAIT2()  asm volatile("cp.async.wait_group 2;")
#define CP_WAIT0()  asm volatile("cp.async.wait_group 0;")

#define LDSM4(r, addr)                                                          \
    asm volatile("ldmatrix.sync.aligned.m8n8.x4.shared.b16 {%0,%1,%2,%3}, [%4];"\
        : "=r"((r)[0]), "=r"((r)[1]), "=r"((r)[2]), "=r"((r)[3]) : "r"(addr))

#define MMAH(d, a, b0, b1)                                                      \
    asm volatile("mma.sync.aligned.m16n8k16.row.col.f32.f16.f16.f32 "           \
        "{%0,%1,%2,%3},{%4,%5,%6,%7},{%8,%9},{%0,%1,%2,%3};"                    \
        : "+f"((d)[0]), "+f"((d)[1]), "+f"((d)[2]), "+f"((d)[3])                \
        : "r"((a)[0]), "r"((a)[1]), "r"((a)[2]), "r"((a)[3]), "r"(b0), "r"(b1))

// ---------------- staging converts ----------------
__global__ void k_convA_direct(const float* __restrict__ A0, const float* __restrict__ A1,
                               const float* __restrict__ A2) {
    int idx = blockIdx.x * 256 + threadIdx.x;
    if (idx >= 3 * 1024 * 1024) return;
    int s = idx >> 20;
    int rem = idx & 0xFFFFF;
    const float* A = (s == 0) ? A0 : ((s == 1) ? A1 : A2);
    g_Bh[idx] = __float2half(A[rem]);
}

__global__ void k_transposeA_conv(const float* __restrict__ A0, const float* __restrict__ A1,
                                  const float* __restrict__ A2) {
    __shared__ float t[32][33];
    int s = blockIdx.z;
    const float* A = (s == 0) ? A0 : ((s == 1) ? A1 : A2);
    int wb = blockIdx.x * 32, vb = blockIdx.y * 32;
#pragma unroll
    for (int j = 0; j < 32; j += 8)
        t[threadIdx.y + j][threadIdx.x] = A[(size_t)(vb + threadIdx.y + j) * 1024 + wb + threadIdx.x];
    __syncthreads();
#pragma unroll
    for (int j = 0; j < 32; j += 8) {
        float f = t[threadIdx.x][threadIdx.y + j];
        __half h = __float2half(f);
        size_t o = (size_t)(s * 2048 + wb + threadIdx.y + j) * 1024 + vb + threadIdx.x;
        g_Abf_h[o] = h;
        g_Abf_l[o] = __float2half(f - __half2float(h));
    }
}

__global__ void k_conv_sq() {
    int idx = blockIdx.x * 256 + threadIdx.x;
    if (idx >= 3 * 1024 * 1024) return;
    int s = idx >> 20;
    int rem = idx & 0xFFFFF;
    int w = rem >> 10, v = rem & 1023;
    g_Abf_h[(size_t)(s * 2048 + 1024 + w) * 1024 + v] = __float2half(g_Asq[idx]);
}

__global__ void k_convX(const float* __restrict__ x) {
    __shared__ float s[512 * 13];
    int bc = blockIdx.x >> 1;
    int vh = blockIdx.x & 1;
    const float* src = x + (size_t)bc * MCOLS + vh * 6656;
    for (int e = threadIdx.x; e < 6656; e += 256) s[e] = src[e];
    __syncthreads();
    for (int e = threadIdx.x; e < 6656; e += 256) {
        int l = e >> 9;
        int vloc = e & 511;
        g_Xh[(size_t)(bc * 13 + l) * 1024 + vh * 512 + vloc] = __float2half(s[vloc * 13 + l]);
    }
}

__global__ void k_convW(const float* __restrict__ W) {
    int idx = blockIdx.x * 256 + threadIdx.x;
    if (idx >= 64 * CIN) return;
    g_Wh[idx] = __float2half(W[idx]);
}

// ---------------- gemm0: (A^T)^2 exact 2-term, BM=128 BN=256 BK=64, 1 CTA/SM ----------------
#define STAGE_B0 65536
#define GEMM_DYN0 (3 * STAGE_B0)

__global__ __launch_bounds__(256, 1) void k_gemm0() {
    extern __shared__ char sm[];
    const uint32_t sbase = smem_u32(sm);
    const int tid = threadIdx.x, lane = tid & 31, wid = tid >> 5;

    int s = blockIdx.z;
    const __half* Ah = g_Abf_h + (size_t)(s * 2048) * 1024;
    const __half* Al = g_Abf_l + (size_t)(s * 2048) * 1024;
    const __half* Bh = g_Bh + ((size_t)s << 20);
    const size_t i0 = (size_t)blockIdx.x * 128;
    const size_t j0 = (size_t)blockIdx.y * 256;

    const int wm = (wid & 1) * 64;
    const int wn = (wid >> 1) * 64;
    const int arow = wm + (lane & 15);
    const int a_x7 = arow & 7;
    const int a_cs = lane >> 4;
    const int brow = wn + ((lane >> 4) << 3) + (lane & 7);
    const int b_x7 = brow & 7;
    const int b_cs = (lane >> 3) & 1;

    float acc[4][8][4];
#pragma unroll
    for (int mt = 0; mt < 4; mt++)
#pragma unroll
        for (int nt = 0; nt < 8; nt++)
#pragma unroll
            for (int q = 0; q < 4; q++) acc[mt][nt][q] = 0.f;

    auto load_stage = [&](int st, int buf) {
        const int kv0 = st * 64;
        const uint32_t sb = sbase + buf * STAGE_B0;
#pragma unroll
        for (int q = 0; q < 4; q++) {
            int id = tid + 256 * q;
            int row = id >> 3, kc = id & 7;
            uint32_t sw = row * 128 + ((kc ^ (row & 7)) << 4);
            size_t go = (i0 + row) * 1024 + kv0 + kc * 8;
            CP16(sb + sw, Ah + go);
            CP16(sb + 16384 + sw, Al + go);
        }
#pragma unroll
        for (int q = 0; q < 8; q++) {
            int id = tid + 256 * q;
            int row = id >> 3, kc = id & 7;
            uint32_t sw = row * 128 + ((kc ^ (row & 7)) << 4);
            CP16(sb + 32768 + sw, Bh + (j0 + row) * 1024 + kv0 + kc * 8);
        }
    };

    load_stage(0, 0); CP_COMMIT();
    load_stage(1, 1); CP_COMMIT();
    load_stage(2, 2); CP_COMMIT();

    int buf = 0;
    for (int st = 0; st < 16; ++st) {
        CP_WAIT2();
        __syncthreads();
        const uint32_t sb = sbase + buf * STAGE_B0;
#pragma unroll
        for (int kk = 0; kk < 4; kk++) {
            uint32_t ah[4][4], al[4][4];
#pragma unroll
            for (int mt = 0; mt < 4; mt++) {
                uint32_t addr = sb + (arow + mt * 16) * 128 + (((kk * 2 + a_cs) ^ a_x7) << 4);
                LDSM4(ah[mt], addr);
                LDSM4(al[mt], addr + 16384);
            }
#pragma unroll
            for (int nt2 = 0; nt2 < 4; nt2++) {
                uint32_t bh[4];
                LDSM4(bh, sb + 32768 + (brow + nt2 * 16) * 128 +
                          (((kk * 2 + b_cs) ^ b_x7) << 4));
#pragma unroll
                for (int mt = 0; mt < 4; mt++) {
                    MMAH(acc[mt][nt2 * 2],     ah[mt], bh[0], bh[1]);
                    MMAH(acc[mt][nt2 * 2 + 1], ah[mt], bh[2], bh[3]);
                    MMAH(acc[mt][nt2 * 2],     al[mt], bh[0], bh[1]);
                    MMAH(acc[mt][nt2 * 2 + 1], al[mt], bh[2], bh[3]);
                }
            }
        }
        __syncthreads();
        if (st + 3 < 16) load_stage(st + 3, buf);
        CP_COMMIT();
        buf = (buf + 1 == 3) ? 0 : buf + 1;
    }

    const int crow = lane >> 2;
    const int ccol = (lane & 3) * 2;
    float* C = g_Asq + ((size_t)s << 20);
#pragma unroll
    for (int mt = 0; mt < 4; mt++) {
        size_t rbase = (i0 + wm + mt * 16 + crow) * 1024 + j0 + wn + ccol;
#pragma unroll
        for (int nt = 0; nt < 8; nt++) {
            float* p = C + rbase + nt * 8;
            *(float2*)p              = make_float2(acc[mt][nt][0], acc[mt][nt][1]);
            *(float2*)(p + 8 * 1024) = make_float2(acc[mt][nt][2], acc[mt][nt][3]);
        }
    }
}

// ---------------- gemm1: diffusion 1-term, BM=128 BN=128 BK=64, 2 CTAs/SM ----------------
#define STAGE_B1 32768          // Ah 16K | Xh 16K
#define GEMM_DYN1 (3 * STAGE_B1)

__global__ __launch_bounds__(256, 2) void k_gemm1() {
    extern __shared__ char sm[];
    const uint32_t sbase = smem_u32(sm);
    const int tid = threadIdx.x, lane = tid & 31, wid = tid >> 5;

    const size_t i0 = (size_t)blockIdx.x * 128;
    const size_t j0 = (size_t)blockIdx.y * 128;

    const int wm = (wid & 1) * 64;
    const int wn = (wid >> 1) * 32;
    const int arow = wm + (lane & 15);
    const int a_x7 = arow & 7;
    const int a_cs = lane >> 4;
    const int brow = wn + ((lane >> 4) << 3) + (lane & 7);
    const int b_x7 = brow & 7;
    const int b_cs = (lane >> 3) & 1;

    float acc[4][4][4];
#pragma unroll
    for (int mt = 0; mt < 4; mt++)
#pragma unroll
        for (int nt = 0; nt < 4; nt++)
#pragma unroll
            for (int q = 0; q < 4; q++) acc[mt][nt][q] = 0.f;

    auto load_stage = [&](int st, int buf) {
        const int kv0 = st * 64;
        const uint32_t sb = sbase + buf * STAGE_B1;
#pragma unroll
        for (int q = 0; q < 4; q++) {
            int id = tid + 256 * q;
            int row = id >> 3, kc = id & 7;
            uint32_t sw = row * 128 + ((kc ^ (row & 7)) << 4);
            CP16(sb + sw, g_Abf_h + (i0 + row) * 1024 + kv0 + kc * 8);
        }
#pragma unroll
        for (int q = 0; q < 4; q++) {
            int id = tid + 256 * q;
            int row = id >> 3, kc = id & 7;
            uint32_t sw = row * 128 + ((kc ^ (row & 7)) << 4);
            CP16(sb + 16384 + sw, g_Xh + (j0 + row) * 1024 + kv0 + kc * 8);
        }
    };

    load_stage(0, 0); CP_COMMIT();
    load_stage(1, 1); CP_COMMIT();
    load_stage(2, 2); CP_COMMIT();

    int buf = 0;
    for (int st = 0; st < 16; ++st) {
        CP_WAIT2();
        __syncthreads();
        const uint32_t sb = sbase + buf * STAGE_B1;
#pragma unroll
        for (int kk = 0; kk < 4; kk++) {
            uint32_t ah[4][4];
#pragma unroll
            for (int mt = 0; mt < 4; mt++)
                LDSM4(ah[mt], sb + (arow + mt * 16) * 128 + (((kk * 2 + a_cs) ^ a_x7) << 4));
#pragma unroll
            for (int nt2 = 0; nt2 < 2; nt2++) {
                uint32_t bh[4];
                LDSM4(bh, sb + 16384 + (brow + nt2 * 16) * 128 +
                          (((kk * 2 + b_cs) ^ b_x7) << 4));
#pragma unroll
                for (int mt = 0; mt < 4; mt++) {
                    MMAH(acc[mt][nt2 * 2],     ah[mt], bh[0], bh[1]);
                    MMAH(acc[mt][nt2 * 2 + 1], ah[mt], bh[2], bh[3]);
                }
            }
        }
        __syncthreads();
        if (st + 3 < 16) load_stage(st + 3, buf);
        CP_COMMIT();
        buf = (buf + 1 == 3) ? 0 : buf + 1;
    }

    const int crow = lane >> 2;
    const int ccol = (lane & 3) * 2;
#pragma unroll
    for (int mt = 0; mt < 4; mt++) {
        size_t rbase = (i0 + wm + mt * 16 + crow) * MCOLS + j0 + wn + ccol;
#pragma unroll
        for (int nt = 0; nt < 4; nt++) {
            __half* p = g_yt + rbase + nt * 8;
            *(__half2*)p               = __floats2half2_rn(acc[mt][nt][0], acc[mt][nt][1]);
            *(__half2*)(p + 8 * MCOLS) = __floats2half2_rn(acc[mt][nt][2], acc[mt][nt][3]);
        }
    }
}

// ---------------- transpose/pack: Hf[(b,v,l)][ct] from x + g_yt ----------------
#define TRANS_DYN (48 * 416 * 2 + 32 * 104 * 4)

__global__ __launch_bounds__(256) void k_trans(const float* __restrict__ x) {
    extern __shared__ char sm[];
    __half* syt = (__half*)sm;
    float*  sx  = (float*)(sm + 48 * 416 * 2);
    const int v0 = blockIdx.x * 8;
    const int b  = blockIdx.y;
    const int tid = threadIdx.x;

    for (int e = tid; e < 48 * 52; e += 256) {
        int r = e / 52, q = e - r * 52;
        int g = r >> 3, vi = r & 7;
        const __half* src = g_yt + ((size_t)(g * 1024 + v0 + vi)) * MCOLS + b * 416 + q * 8;
        *(uint4*)(syt + r * 416 + q * 8) = *(const uint4*)src;
    }
    for (int e = tid; e < 32 * 26; e += 256) {
        int c = e / 26, q = e - c * 26;
        const float* src = x + (size_t)(b * 32 + c) * MCOLS + v0 * 13 + q * 4;
        *(float4*)(sx + c * 104 + q * 4) = *(const float4*)src;
    }
    __syncthreads();

    for (int e = tid; e < 104 * 28; e += 256) {
        int n = e / 28, q = e - n * 28;
        int vi = n / 13, l = n - vi * 13;
        int ct0 = q * 8;
        union { uint4 u; __half2 h[4]; } pk;
        if (q < 4) {
            int c0 = ct0;
#pragma unroll
            for (int i = 0; i < 4; i++)
                pk.h[i] = __floats2half2_rn(sx[(c0 + 2 * i) * 104 + n],
                                            sx[(c0 + 2 * i + 1) * 104 + n]);
        } else {
            int g = ct0 >> 5, c0 = ct0 & 31;
            const __half* row = syt + ((g - 1) * 8 + vi) * 416 + l;
#pragma unroll
            for (int i = 0; i < 4; i++)
                pk.h[i] = __halves2half2(row[(c0 + 2 * i) * 13], row[(c0 + 2 * i + 1) * 13]);
        }
        *(uint4*)(g_Hf + ((size_t)(b * MCOLS + v0 * 13 + n)) * CIN + ct0) = pk.u;
    }
}

// ---------------- final MMA: out = Wh * Hf + bias (1-term W), 2 CTAs/SM ----------------
#define FIN_W    0
#define FIN_HS   (64 * PAD_E * 2)               // 29696
#define FIN_DYN  (FIN_HS + 128 * PAD_E * 2)     // 89088

__global__ __launch_bounds__(256, 2) void k_final(const float* __restrict__ bias,
                                                  float* __restrict__ out) {
    extern __shared__ char sm[];
    const uint32_t sbase = smem_u32(sm);
    const int tid = threadIdx.x, lane = tid & 31, wid = tid >> 5;
    const int b = blockIdx.y;
    const int j0 = blockIdx.x * 128;

    for (int e = tid; e < 64 * 28; e += 256) {
        int r = e / 28, q = e - r * 28;
        CP16(sbase + FIN_W + r * 464 + q * 16, g_Wh + r * CIN + q * 8);
    }
    for (int e = tid; e < 128 * 28; e += 256) {
        int r = e / 28, q = e - r * 28;
        CP16(sbase + FIN_HS + r * 464 + q * 16,
             g_Hf + ((size_t)(b * MCOLS + j0 + r)) * CIN + q * 8);
    }
    CP_COMMIT();
    CP_WAIT0();
    __syncthreads();

    const int wm = (wid & 1) * 32;
    const int wn = (wid >> 1) * 32;
    const int arow_l = lane & 15;
    const int a_cs = lane >> 4;
    const int brow_l = ((lane >> 4) << 3) + (lane & 7);
    const int b_cs = (lane >> 3) & 1;

    float acc[2][4][4];
#pragma unroll
    for (int mt = 0; mt < 2; mt++)
#pragma unroll
        for (int nt = 0; nt < 4; nt++)
#pragma unroll
            for (int q = 0; q < 4; q++) acc[mt][nt][q] = 0.f;

#pragma unroll
    for (int kc = 0; kc < 14; kc++) {
        uint32_t wh[2][4];
#pragma unroll
        for (int mt = 0; mt < 2; mt++)
            LDSM4(wh[mt], sbase + FIN_W + (wm + mt * 16 + arow_l) * 464 + (kc * 2 + a_cs) * 16);
#pragma unroll
        for (int nt2 = 0; nt2 < 2; nt2++) {
            uint32_t bh[4];
            LDSM4(bh, sbase + FIN_HS + (wn + nt2 * 16 + brow_l) * 464 +
                      (kc * 2 + b_cs) * 16);
#pragma unroll
            for (int mt = 0; mt < 2; mt++) {
                MMAH(acc[mt][nt2 * 2],     wh[mt], bh[0], bh[1]);
                MMAH(acc[mt][nt2 * 2 + 1], wh[mt], bh[2], bh[3]);
            }
        }
    }

    const int crow = lane >> 2;
    const int ccol = (lane & 3) * 2;
#pragma unroll
    for (int mt = 0; mt < 2; mt++) {
        int o = wm + mt * 16 + crow;
        float b0 = bias[o], b1 = bias[o + 8];
        size_t r0 = (size_t)(b * 64 + o) * MCOLS + j0 + wn + ccol;
#pragma unroll
        for (int nt = 0; nt < 4; nt++) {
            float* p = out + r0 + nt * 8;
            *(float2*)p               = make_float2(acc[mt][nt][0] + b0, acc[mt][nt][1] + b0);
            *(float2*)(p + 8 * MCOLS) = make_float2(acc[mt][nt][2] + b1, acc[mt][nt][3] + b1);
        }
    }
}

// ---------------- launcher ----------------
extern "C" void kernel_launch(void* const* d_in, const int* in_sizes, int n_in,
                              void* d_out, int out_size) {
    const float* x    = (const float*)d_in[0];
    const float* A0   = (const float*)d_in[1];
    const float* A1   = (const float*)d_in[2];
    const float* A2   = (const float*)d_in[3];
    const float* W    = (const float*)d_in[4];
    const float* bias = (const float*)d_in[5];
    float* out = (float*)d_out;

    cudaFuncSetAttribute(k_gemm0, cudaFuncAttributeMaxDynamicSharedMemorySize, GEMM_DYN0);
    cudaFuncSetAttribute(k_gemm1, cudaFuncAttributeMaxDynamicSharedMemorySize, GEMM_DYN1);
    cudaFuncSetAttribute(k_trans, cudaFuncAttributeMaxDynamicSharedMemorySize, TRANS_DYN);
    cudaFuncSetAttribute(k_final, cudaFuncAttributeMaxDynamicSharedMemorySize, FIN_DYN);

    k_convA_direct<<<(3 * 1024 * 1024 + 255) / 256, 256>>>(A0, A1, A2);
    k_transposeA_conv<<<dim3(32, 32, 3), dim3(32, 8)>>>(A0, A1, A2);
    k_convX<<<2048, 256>>>(x);
    k_convW<<<56, 256>>>(W);

    k_gemm0<<<dim3(8, 4, 3), 256, GEMM_DYN0>>>();
    k_conv_sq<<<(3 * 1024 * 1024 + 255) / 256, 256>>>();

    k_gemm1<<<dim3(48, 104), 256, GEMM_DYN1>>>();

    k_trans<<<dim3(128, 32), 256, TRANS_DYN>>>(x);
    k_final<<<dim3(104, 32), 256, FIN_DYN>>>(bias, out);
}

// round 10
// speedup vs baseline: 2.0120x; 1.2102x over previous
#include <cuda_runtime.h>
#include <cuda_fp16.h>
#include <cstdint>

// GraphConvNet: B=32, C=32, V=1024, L=13, support=3, order=2
// X column order m' = (b,l,c) so yt[(g,v)][b,l,c] has c contiguous -> k_final reads yt directly.
// gemm1 1-term fp16 (2 CTAs/SM); A^2 exact 2-term; W 1-term fp16.

#define V_N   1024
#define MCOLS 13312
#define MI    6144
#define CIN   224
#define NB    32
#define PAD_E 232

// ---------------- scratch ----------------
__device__ float  g_Asq[3u * 1024u * 1024u];
__device__ __align__(16) __half g_yt [(size_t)MI * MCOLS];      // [i=(g,v)][m'=(b,l,c)]
__device__ __align__(16) __half g_Abf_h[(size_t)MI * V_N];
__device__ __align__(16) __half g_Abf_l[(size_t)MI * V_N];
__device__ __align__(16) __half g_Bh [3u * 1024u * 1024u];
__device__ __align__(16) __half g_Xh [(size_t)MCOLS * V_N];     // [m'=(b,l,c)][v]
__device__ __align__(16) __half g_Xt [(size_t)NB * MCOLS * 32]; // [(b,v,l)][c]
__device__ __align__(16) __half g_Wh [64 * CIN];

// ================= helpers =================
__device__ __forceinline__ uint32_t smem_u32(const void* p) {
    uint32_t a;
    asm("{ .reg .u64 t; cvta.to.shared.u64 t, %1; cvt.u32.u64 %0, t; }" : "=r"(a) : "l"(p));
    return a;
}
#define CP16(s, g) asm volatile("cp.async.cg.shared.global [%0], [%1], 16;" :: "r"(s), "l"(g))
#define CP_COMMIT() asm volatile("cp.async.commit_group;")
#define CP_WAIT2()  asm volatile("cp.async.wait_group 2;")
#define CP_WAIT0()  asm volatile("cp.async.wait_group 0;")

#define LDSM4(r, addr)                                                          \
    asm volatile("ldmatrix.sync.aligned.m8n8.x4.shared.b16 {%0,%1,%2,%3}, [%4];"\
        : "=r"((r)[0]), "=r"((r)[1]), "=r"((r)[2]), "=r"((r)[3]) : "r"(addr))

#define MMAH(d, a, b0, b1)                                                      \
    asm volatile("mma.sync.aligned.m16n8k16.row.col.f32.f16.f16.f32 "           \
        "{%0,%1,%2,%3},{%4,%5,%6,%7},{%8,%9},{%0,%1,%2,%3};"                    \
        : "+f"((d)[0]), "+f"((d)[1]), "+f"((d)[2]), "+f"((d)[3])                \
        : "r"((a)[0]), "r"((a)[1]), "r"((a)[2]), "r"((a)[3]), "r"(b0), "r"(b1))

// ---------------- staging converts ----------------
__global__ void k_convA_direct(const float* __restrict__ A0, const float* __restrict__ A1,
                               const float* __restrict__ A2) {
    int idx = blockIdx.x * 256 + threadIdx.x;
    if (idx >= 3 * 1024 * 1024) return;
    int s = idx >> 20;
    int rem = idx & 0xFFFFF;
    const float* A = (s == 0) ? A0 : ((s == 1) ? A1 : A2);
    g_Bh[idx] = __float2half(A[rem]);
}

__global__ void k_transposeA_conv(const float* __restrict__ A0, const float* __restrict__ A1,
                                  const float* __restrict__ A2) {
    __shared__ float t[32][33];
    int s = blockIdx.z;
    const float* A = (s == 0) ? A0 : ((s == 1) ? A1 : A2);
    int wb = blockIdx.x * 32, vb = blockIdx.y * 32;
#pragma unroll
    for (int j = 0; j < 32; j += 8)
        t[threadIdx.y + j][threadIdx.x] = A[(size_t)(vb + threadIdx.y + j) * 1024 + wb + threadIdx.x];
    __syncthreads();
#pragma unroll
    for (int j = 0; j < 32; j += 8) {
        float f = t[threadIdx.x][threadIdx.y + j];
        __half h = __float2half(f);
        size_t o = (size_t)(s * 2048 + wb + threadIdx.y + j) * 1024 + vb + threadIdx.x;
        g_Abf_h[o] = h;
        g_Abf_l[o] = __float2half(f - __half2float(h));
    }
}

__global__ void k_conv_sq() {
    int idx = blockIdx.x * 256 + threadIdx.x;
    if (idx >= 3 * 1024 * 1024) return;
    int s = idx >> 20;
    int rem = idx & 0xFFFFF;
    int w = rem >> 10, v = rem & 1023;
    g_Abf_h[(size_t)(s * 2048 + 1024 + w) * 1024 + v] = __float2half(g_Asq[idx]);
}

// x[bc][v][l] -> g_Xh[m' = b*416 + l*32 + c][v]
__global__ void k_convX(const float* __restrict__ x) {
    __shared__ float s[512 * 13];
    int bc = blockIdx.x >> 1;
    int vh = blockIdx.x & 1;
    int b = bc >> 5, c = bc & 31;
    const float* src = x + (size_t)bc * MCOLS + vh * 6656;
    for (int e = threadIdx.x; e < 6656; e += 256) s[e] = src[e];
    __syncthreads();
    for (int e = threadIdx.x; e < 6656; e += 256) {
        int l = e >> 9;
        int vloc = e & 511;
        g_Xh[(size_t)(b * 416 + l * 32 + c) * 1024 + vh * 512 + vloc] =
            __float2half(s[vloc * 13 + l]);
    }
}

// x[b][c][v,l] -> g_Xt[(b,v,l)][c] fp16  (16 v per block)
__global__ __launch_bounds__(256) void k_convXt(const float* __restrict__ x) {
    __shared__ float sx[32][212];   // pitch 212 floats = 848B, 16B-aligned rows
    int b = blockIdx.y, v0 = blockIdx.x * 16;
    int tid = threadIdx.x;
    for (int e = tid; e < 32 * 52; e += 256) {
        int c = e / 52, q = e - c * 52;
        *(float4*)&sx[c][q * 4] =
            *(const float4*)(x + (size_t)(b * 32 + c) * MCOLS + v0 * 13 + q * 4);
    }
    __syncthreads();
    for (int e = tid; e < 208 * 4; e += 256) {
        int n = e >> 2, ch = e & 3;
        union { uint4 u; __half2 h[4]; } pk;
#pragma unroll
        for (int i = 0; i < 4; i++)
            pk.h[i] = __floats2half2_rn(sx[ch * 8 + 2 * i][n], sx[ch * 8 + 2 * i + 1][n]);
        *(uint4*)(g_Xt + ((size_t)b * MCOLS + v0 * 13 + n) * 32 + ch * 8) = pk.u;
    }
}

__global__ void k_convW(const float* __restrict__ W) {
    int idx = blockIdx.x * 256 + threadIdx.x;
    if (idx >= 64 * CIN) return;
    g_Wh[idx] = __float2half(W[idx]);
}

// ---------------- gemm0: (A^T)^2 exact 2-term ----------------
#define STAGE_B0 65536
#define GEMM_DYN0 (3 * STAGE_B0)

__global__ __launch_bounds__(256, 1) void k_gemm0() {
    extern __shared__ char sm[];
    const uint32_t sbase = smem_u32(sm);
    const int tid = threadIdx.x, lane = tid & 31, wid = tid >> 5;

    int s = blockIdx.z;
    const __half* Ah = g_Abf_h + (size_t)(s * 2048) * 1024;
    const __half* Al = g_Abf_l + (size_t)(s * 2048) * 1024;
    const __half* Bh = g_Bh + ((size_t)s << 20);
    const size_t i0 = (size_t)blockIdx.x * 128;
    const size_t j0 = (size_t)blockIdx.y * 256;

    const int wm = (wid & 1) * 64;
    const int wn = (wid >> 1) * 64;
    const int arow = wm + (lane & 15);
    const int a_x7 = arow & 7;
    const int a_cs = lane >> 4;
    const int brow = wn + ((lane >> 4) << 3) + (lane & 7);
    const int b_x7 = brow & 7;
    const int b_cs = (lane >> 3) & 1;

    float acc[4][8][4];
#pragma unroll
    for (int mt = 0; mt < 4; mt++)
#pragma unroll
        for (int nt = 0; nt < 8; nt++)
#pragma unroll
            for (int q = 0; q < 4; q++) acc[mt][nt][q] = 0.f;

    auto load_stage = [&](int st, int buf) {
        const int kv0 = st * 64;
        const uint32_t sb = sbase + buf * STAGE_B0;
#pragma unroll
        for (int q = 0; q < 4; q++) {
            int id = tid + 256 * q;
            int row = id >> 3, kc = id & 7;
            uint32_t sw = row * 128 + ((kc ^ (row & 7)) << 4);
            size_t go = (i0 + row) * 1024 + kv0 + kc * 8;
            CP16(sb + sw, Ah + go);
            CP16(sb + 16384 + sw, Al + go);
        }
#pragma unroll
        for (int q = 0; q < 8; q++) {
            int id = tid + 256 * q;
            int row = id >> 3, kc = id & 7;
            uint32_t sw = row * 128 + ((kc ^ (row & 7)) << 4);
            CP16(sb + 32768 + sw, Bh + (j0 + row) * 1024 + kv0 + kc * 8);
        }
    };

    load_stage(0, 0); CP_COMMIT();
    load_stage(1, 1); CP_COMMIT();
    load_stage(2, 2); CP_COMMIT();

    int buf = 0;
    for (int st = 0; st < 16; ++st) {
        CP_WAIT2();
        __syncthreads();
        const uint32_t sb = sbase + buf * STAGE_B0;
#pragma unroll
        for (int kk = 0; kk < 4; kk++) {
            uint32_t ah[4][4], al[4][4];
#pragma unroll
            for (int mt = 0; mt < 4; mt++) {
                uint32_t addr = sb + (arow + mt * 16) * 128 + (((kk * 2 + a_cs) ^ a_x7) << 4);
                LDSM4(ah[mt], addr);
                LDSM4(al[mt], addr + 16384);
            }
#pragma unroll
            for (int nt2 = 0; nt2 < 4; nt2++) {
                uint32_t bh[4];
                LDSM4(bh, sb + 32768 + (brow + nt2 * 16) * 128 +
                          (((kk * 2 + b_cs) ^ b_x7) << 4));
#pragma unroll
                for (int mt = 0; mt < 4; mt++) {
                    MMAH(acc[mt][nt2 * 2],     ah[mt], bh[0], bh[1]);
                    MMAH(acc[mt][nt2 * 2 + 1], ah[mt], bh[2], bh[3]);
                    MMAH(acc[mt][nt2 * 2],     al[mt], bh[0], bh[1]);
                    MMAH(acc[mt][nt2 * 2 + 1], al[mt], bh[2], bh[3]);
                }
            }
        }
        __syncthreads();
        if (st + 3 < 16) load_stage(st + 3, buf);
        CP_COMMIT();
        buf = (buf + 1 == 3) ? 0 : buf + 1;
    }

    const int crow = lane >> 2;
    const int ccol = (lane & 3) * 2;
    float* C = g_Asq + ((size_t)s << 20);
#pragma unroll
    for (int mt = 0; mt < 4; mt++) {
        size_t rbase = (i0 + wm + mt * 16 + crow) * 1024 + j0 + wn + ccol;
#pragma unroll
        for (int nt = 0; nt < 8; nt++) {
            float* p = C + rbase + nt * 8;
            *(float2*)p              = make_float2(acc[mt][nt][0], acc[mt][nt][1]);
            *(float2*)(p + 8 * 1024) = make_float2(acc[mt][nt][2], acc[mt][nt][3]);
        }
    }
}

// ---------------- gemm1: diffusion 1-term, BM=128 BN=128 BK=64, 2 CTAs/SM ----------------
#define STAGE_B1 32768
#define GEMM_DYN1 (3 * STAGE_B1)

__global__ __launch_bounds__(256, 2) void k_gemm1() {
    extern __shared__ char sm[];
    const uint32_t sbase = smem_u32(sm);
    const int tid = threadIdx.x, lane = tid & 31, wid = tid >> 5;

    const size_t i0 = (size_t)blockIdx.x * 128;
    const size_t j0 = (size_t)blockIdx.y * 128;

    const int wm = (wid & 1) * 64;
    const int wn = (wid >> 1) * 32;
    const int arow = wm + (lane & 15);
    const int a_x7 = arow & 7;
    const int a_cs = lane >> 4;
    const int brow = wn + ((lane >> 4) << 3) + (lane & 7);
    const int b_x7 = brow & 7;
    const int b_cs = (lane >> 3) & 1;

    float acc[4][4][4];
#pragma unroll
    for (int mt = 0; mt < 4; mt++)
#pragma unroll
        for (int nt = 0; nt < 4; nt++)
#pragma unroll
            for (int q = 0; q < 4; q++) acc[mt][nt][q] = 0.f;

    auto load_stage = [&](int st, int buf) {
        const int kv0 = st * 64;
        const uint32_t sb = sbase + buf * STAGE_B1;
#pragma unroll
        for (int q = 0; q < 4; q++) {
            int id = tid + 256 * q;
            int row = id >> 3, kc = id & 7;
            uint32_t sw = row * 128 + ((kc ^ (row & 7)) << 4);
            CP16(sb + sw, g_Abf_h + (i0 + row) * 1024 + kv0 + kc * 8);
        }
#pragma unroll
        for (int q = 0; q < 4; q++) {
            int id = tid + 256 * q;
            int row = id >> 3, kc = id & 7;
            uint32_t sw = row * 128 + ((kc ^ (row & 7)) << 4);
            CP16(sb + 16384 + sw, g_Xh + (j0 + row) * 1024 + kv0 + kc * 8);
        }
    };

    load_stage(0, 0); CP_COMMIT();
    load_stage(1, 1); CP_COMMIT();
    load_stage(2, 2); CP_COMMIT();

    int buf = 0;
    for (int st = 0; st < 16; ++st) {
        CP_WAIT2();
        __syncthreads();
        const uint32_t sb = sbase + buf * STAGE_B1;
#pragma unroll
        for (int kk = 0; kk < 4; kk++) {
            uint32_t ah[4][4];
#pragma unroll
            for (int mt = 0; mt < 4; mt++)
                LDSM4(ah[mt], sb + (arow + mt * 16) * 128 + (((kk * 2 + a_cs) ^ a_x7) << 4));
#pragma unroll
            for (int nt2 = 0; nt2 < 2; nt2++) {
                uint32_t bh[4];
                LDSM4(bh, sb + 16384 + (brow + nt2 * 16) * 128 +
                          (((kk * 2 + b_cs) ^ b_x7) << 4));
#pragma unroll
                for (int mt = 0; mt < 4; mt++) {
                    MMAH(acc[mt][nt2 * 2],     ah[mt], bh[0], bh[1]);
                    MMAH(acc[mt][nt2 * 2 + 1], ah[mt], bh[2], bh[3]);
                }
            }
        }
        __syncthreads();
        if (st + 3 < 16) load_stage(st + 3, buf);
        CP_COMMIT();
        buf = (buf + 1 == 3) ? 0 : buf + 1;
    }

    const int crow = lane >> 2;
    const int ccol = (lane & 3) * 2;
#pragma unroll
    for (int mt = 0; mt < 4; mt++) {
        size_t rbase = (i0 + wm + mt * 16 + crow) * MCOLS + j0 + wn + ccol;
#pragma unroll
        for (int nt = 0; nt < 4; nt++) {
            __half* p = g_yt + rbase + nt * 8;
            *(__half2*)p               = __floats2half2_rn(acc[mt][nt][0], acc[mt][nt][1]);
            *(__half2*)(p + 8 * MCOLS) = __floats2half2_rn(acc[mt][nt][2], acc[mt][nt][3]);
        }
    }
}

// ---------------- final MMA: out = Wh * H + bias; H gathered from g_Xt + g_yt ----------------
#define FIN_W    0
#define FIN_HS   (64 * PAD_E * 2)               // 29696
#define FIN_DYN  (FIN_HS + 128 * PAD_E * 2)     // 89088

__global__ __launch_bounds__(256, 2) void k_final(const float* __restrict__ bias,
                                                  float* __restrict__ out) {
    extern __shared__ char sm[];
    const uint32_t sbase = smem_u32(sm);
    const int tid = threadIdx.x, lane = tid & 31, wid = tid >> 5;
    const int b = blockIdx.y;
    const int j0 = blockIdx.x * 128;

    // W: 64 rows x 28 chunks
    for (int e = tid; e < 64 * 28; e += 256) {
        int r = e / 28, q = e - r * 28;
        CP16(sbase + FIN_W + r * 464 + q * 16, g_Wh + r * CIN + q * 8);
    }
    // H: 128 rows x 28 chunks; q<4 from g_Xt, q>=4 from g_yt (c contiguous)
    for (int e = tid; e < 128 * 28; e += 256) {
        int r = e / 28, q = e - r * 28;
        int n = j0 + r;
        int v = n / 13, l = n - v * 13;
        const __half* src;
        if (q < 4)
            src = g_Xt + ((size_t)b * MCOLS + n) * 32 + q * 8;
        else {
            int g = (q - 4) >> 2, ch = (q - 4) & 3;
            src = g_yt + ((size_t)(g * 1024 + v)) * MCOLS + b * 416 + l * 32 + ch * 8;
        }
        CP16(sbase + FIN_HS + r * 464 + q * 16, src);
    }
    CP_COMMIT();
    CP_WAIT0();
    __syncthreads();

    const int wm = (wid & 1) * 32;
    const int wn = (wid >> 1) * 32;
    const int arow_l = lane & 15;
    const int a_cs = lane >> 4;
    const int brow_l = ((lane >> 4) << 3) + (lane & 7);
    const int b_cs = (lane >> 3) & 1;

    float acc[2][4][4];
#pragma unroll
    for (int mt = 0; mt < 2; mt++)
#pragma unroll
        for (int nt = 0; nt < 4; nt++)
#pragma unroll
            for (int q = 0; q < 4; q++) acc[mt][nt][q] = 0.f;

#pragma unroll
    for (int kc = 0; kc < 14; kc++) {
        uint32_t wh[2][4];
#pragma unroll
        for (int mt = 0; mt < 2; mt++)
            LDSM4(wh[mt], sbase + FIN_W + (wm + mt * 16 + arow_l) * 464 + (kc * 2 + a_cs) * 16);
#pragma unroll
        for (int nt2 = 0; nt2 < 2; nt2++) {
            uint32_t bh[4];
            LDSM4(bh, sbase + FIN_HS + (wn + nt2 * 16 + brow_l) * 464 +
                      (kc * 2 + b_cs) * 16);
#pragma unroll
            for (int mt = 0; mt < 2; mt++) {
                MMAH(acc[mt][nt2 * 2],     wh[mt], bh[0], bh[1]);
                MMAH(acc[mt][nt2 * 2 + 1], wh[mt], bh[2], bh[3]);
            }
        }
    }

    const int crow = lane >> 2;
    const int ccol = (lane & 3) * 2;
#pragma unroll
    for (int mt = 0; mt < 2; mt++) {
        int o = wm + mt * 16 + crow;
        float b0 = bias[o], b1 = bias[o + 8];
        size_t r0 = (size_t)(b * 64 + o) * MCOLS + j0 + wn + ccol;
#pragma unroll
        for (int nt = 0; nt < 4; nt++) {
            float* p = out + r0 + nt * 8;
            *(float2*)p               = make_float2(acc[mt][nt][0] + b0, acc[mt][nt][1] + b0);
            *(float2*)(p + 8 * MCOLS) = make_float2(acc[mt][nt][2] + b1, acc[mt][nt][3] + b1);
        }
    }
}

// ---------------- launcher ----------------
extern "C" void kernel_launch(void* const* d_in, const int* in_sizes, int n_in,
                              void* d_out, int out_size) {
    const float* x    = (const float*)d_in[0];
    const float* A0   = (const float*)d_in[1];
    const float* A1   = (const float*)d_in[2];
    const float* A2   = (const float*)d_in[3];
    const float* W    = (const float*)d_in[4];
    const float* bias = (const float*)d_in[5];
    float* out = (float*)d_out;

    cudaFuncSetAttribute(k_gemm0, cudaFuncAttributeMaxDynamicSharedMemorySize, GEMM_DYN0);
    cudaFuncSetAttribute(k_gemm1, cudaFuncAttributeMaxDynamicSharedMemorySize, GEMM_DYN1);
    cudaFuncSetAttribute(k_final, cudaFuncAttributeMaxDynamicSharedMemorySize, FIN_DYN);

    k_convA_direct<<<(3 * 1024 * 1024 + 255) / 256, 256>>>(A0, A1, A2);
    k_transposeA_conv<<<dim3(32, 32, 3), dim3(32, 8)>>>(A0, A1, A2);
    k_convX<<<2048, 256>>>(x);
    k_convXt<<<dim3(64, 32), 256>>>(x);
    k_convW<<<56, 256>>>(W);

    k_gemm0<<<dim3(8, 4, 3), 256, GEMM_DYN0>>>();
    k_conv_sq<<<(3 * 1024 * 1024 + 255) / 256, 256>>>();

    k_gemm1<<<dim3(48, 104), 256, GEMM_DYN1>>>();

    k_final<<<dim3(104, 32), 256, FIN_DYN>>>(bias, out);
}

// round 11
// speedup vs baseline: 2.1003x; 1.0439x over previous
#include <cuda_runtime.h>
#include <cuda_fp16.h>
#include <cstdint>

// GraphConvNet: B=32, C=32, V=1024, L=13, support=3, order=2
// X column order m' = (b,l,c); yt[(g,v)][b,l,c] read directly by k_final.
// gemm1 1-term fp16 (2 CTAs/SM); A^2 exact 2-term fused-convert epilogue; W 1-term fp16.

#define V_N   1024
#define MCOLS 13312
#define MI    6144
#define CIN   224
#define NB    32
#define PAD_E 232

// ---------------- scratch ----------------
__device__ __align__(16) __half g_yt [(size_t)MI * MCOLS];      // [i=(g,v)][m'=(b,l,c)]
__device__ __align__(16) __half g_Abf_h[(size_t)MI * V_N];
__device__ __align__(16) __half g_Abf_l[(size_t)MI * V_N];      // only rows [s*2048, s*2048+1024)
__device__ __align__(16) __half g_Bh [3u * 1024u * 1024u];
__device__ __align__(16) __half g_Xh [(size_t)MCOLS * V_N];     // [m'=(b,l,c)][v]
__device__ __align__(16) __half g_Xt [(size_t)NB * MCOLS * 32]; // [(b,v,l)][c]
__device__ __align__(16) __half g_Wh [64 * CIN];

// ================= helpers =================
__device__ __forceinline__ uint32_t smem_u32(const void* p) {
    uint32_t a;
    asm("{ .reg .u64 t; cvta.to.shared.u64 t, %1; cvt.u32.u64 %0, t; }" : "=r"(a) : "l"(p));
    return a;
}
#define CP16(s, g) asm volatile("cp.async.cg.shared.global [%0], [%1], 16;" :: "r"(s), "l"(g))
#define CP_COMMIT() asm volatile("cp.async.commit_group;")
#define CP_WAIT2()  asm volatile("cp.async.wait_group 2;")
#define CP_WAIT1()  asm volatile("cp.async.wait_group 1;")
#define CP_WAIT0()  asm volatile("cp.async.wait_group 0;")

#define LDSM4(r, addr)                                                          \
    asm volatile("ldmatrix.sync.aligned.m8n8.x4.shared.b16 {%0,%1,%2,%3}, [%4];"\
        : "=r"((r)[0]), "=r"((r)[1]), "=r"((r)[2]), "=r"((r)[3]) : "r"(addr))

#define MMAH(d, a, b0, b1)                                                      \
    asm volatile("mma.sync.aligned.m16n8k16.row.col.f32.f16.f16.f32 "           \
        "{%0,%1,%2,%3},{%4,%5,%6,%7},{%8,%9},{%0,%1,%2,%3};"                    \
        : "+f"((d)[0]), "+f"((d)[1]), "+f"((d)[2]), "+f"((d)[3])                \
        : "r"((a)[0]), "r"((a)[1]), "r"((a)[2]), "r"((a)[3]), "r"(b0), "r"(b1))

// ---------------- A: transpose+split-convert, and direct fp16 copy (fused) ----------------
__global__ void k_stageA(const float* __restrict__ A0, const float* __restrict__ A1,
                         const float* __restrict__ A2) {
    __shared__ float t[32][33];
    int s = blockIdx.z;
    const float* A = (s == 0) ? A0 : ((s == 1) ? A1 : A2);
    int wb = blockIdx.x * 32, vb = blockIdx.y * 32;
#pragma unroll
    for (int j = 0; j < 32; j += 8) {
        float f = A[(size_t)(vb + threadIdx.y + j) * 1024 + wb + threadIdx.x];
        t[threadIdx.y + j][threadIdx.x] = f;
        // direct fp16 copy (A row-major) for gemm0's B operand
        g_Bh[((size_t)s << 20) + (size_t)(vb + threadIdx.y + j) * 1024 + wb + threadIdx.x] =
            __float2half(f);
    }
    __syncthreads();
#pragma unroll
    for (int j = 0; j < 32; j += 8) {
        float f = t[threadIdx.x][threadIdx.y + j];     // A[vb+tx][wb+ty+j]
        __half h = __float2half(f);
        size_t o = (size_t)(s * 2048 + wb + threadIdx.y + j) * 1024 + vb + threadIdx.x;
        g_Abf_h[o] = h;
        g_Abf_l[o] = __float2half(f - __half2float(h));
    }
}

// ---------------- x -> g_Xh[m'][v] and g_Xt[(b,v,l)][c]  (single pass) ----------------
__global__ __launch_bounds__(256) void k_stageX(const float* __restrict__ x) {
    __shared__ float sx[32][212];   // pitch 212 floats = 848B, 16B-aligned rows
    int b = blockIdx.y, v0 = blockIdx.x * 16;
    int tid = threadIdx.x;
    for (int e = tid; e < 32 * 52; e += 256) {
        int c = e / 52, q = e - c * 52;
        *(float4*)&sx[c][q * 4] =
            *(const float4*)(x + (size_t)(b * 32 + c) * MCOLS + v0 * 13 + q * 4);
    }
    __syncthreads();
    // g_Xt: [(b,v,l)][c]
    for (int e = tid; e < 208 * 4; e += 256) {
        int n = e >> 2, ch = e & 3;
        union { uint4 u; __half2 h[4]; } pk;
#pragma unroll
        for (int i = 0; i < 4; i++)
            pk.h[i] = __floats2half2_rn(sx[ch * 8 + 2 * i][n], sx[ch * 8 + 2 * i + 1][n]);
        *(uint4*)(g_Xt + ((size_t)b * MCOLS + v0 * 13 + n) * 32 + ch * 8) = pk.u;
    }
    // g_Xh: row r = l*32+c of this b, columns v0..v0+15 (two 8-half chunks)
    for (int e = tid; e < 416 * 2; e += 256) {
        int r = e >> 1, vi0 = (e & 1) * 8;
        int l = r >> 5, c = r & 31;
        union { uint4 u; __half2 h[4]; } pk;
#pragma unroll
        for (int i = 0; i < 4; i++)
            pk.h[i] = __floats2half2_rn(sx[c][(vi0 + 2 * i) * 13 + l],
                                        sx[c][(vi0 + 2 * i + 1) * 13 + l]);
        *(uint4*)(g_Xh + (size_t)(b * 416 + r) * 1024 + v0 + vi0) = pk.u;
    }
}

__global__ void k_convW(const float* __restrict__ W) {
    int idx = blockIdx.x * 256 + threadIdx.x;
    if (idx >= 64 * CIN) return;
    g_Wh[idx] = __float2half(W[idx]);
}

// ---------------- gemm0: (A^T)^2 exact 2-term, fp16 epilogue into g_Abf_h ----------------
#define STAGE_B0 65536
#define GEMM_DYN0 (3 * STAGE_B0)

__global__ __launch_bounds__(256, 1) void k_gemm0() {
    extern __shared__ char sm[];
    const uint32_t sbase = smem_u32(sm);
    const int tid = threadIdx.x, lane = tid & 31, wid = tid >> 5;

    int s = blockIdx.z;
    const __half* Ah = g_Abf_h + (size_t)(s * 2048) * 1024;
    const __half* Al = g_Abf_l + (size_t)(s * 2048) * 1024;
    const __half* Bh = g_Bh + ((size_t)s << 20);
    const size_t i0 = (size_t)blockIdx.x * 128;
    const size_t j0 = (size_t)blockIdx.y * 256;

    const int wm = (wid & 1) * 64;
    const int wn = (wid >> 1) * 64;
    const int arow = wm + (lane & 15);
    const int a_x7 = arow & 7;
    const int a_cs = lane >> 4;
    const int brow = wn + ((lane >> 4) << 3) + (lane & 7);
    const int b_x7 = brow & 7;
    const int b_cs = (lane >> 3) & 1;

    float acc[4][8][4];
#pragma unroll
    for (int mt = 0; mt < 4; mt++)
#pragma unroll
        for (int nt = 0; nt < 8; nt++)
#pragma unroll
            for (int q = 0; q < 4; q++) acc[mt][nt][q] = 0.f;

    auto load_stage = [&](int st, int buf) {
        const int kv0 = st * 64;
        const uint32_t sb = sbase + buf * STAGE_B0;
#pragma unroll
        for (int q = 0; q < 4; q++) {
            int id = tid + 256 * q;
            int row = id >> 3, kc = id & 7;
            uint32_t sw = row * 128 + ((kc ^ (row & 7)) << 4);
            size_t go = (i0 + row) * 1024 + kv0 + kc * 8;
            CP16(sb + sw, Ah + go);
            CP16(sb + 16384 + sw, Al + go);
        }
#pragma unroll
        for (int q = 0; q < 8; q++) {
            int id = tid + 256 * q;
            int row = id >> 3, kc = id & 7;
            uint32_t sw = row * 128 + ((kc ^ (row & 7)) << 4);
            CP16(sb + 32768 + sw, Bh + (j0 + row) * 1024 + kv0 + kc * 8);
        }
    };

    load_stage(0, 0); CP_COMMIT();
    load_stage(1, 1); CP_COMMIT();
    load_stage(2, 2); CP_COMMIT();

    int buf = 0;
    for (int st = 0; st < 16; ++st) {
        CP_WAIT2();
        __syncthreads();
        const uint32_t sb = sbase + buf * STAGE_B0;
#pragma unroll
        for (int kk = 0; kk < 4; kk++) {
            uint32_t ah[4][4], al[4][4];
#pragma unroll
            for (int mt = 0; mt < 4; mt++) {
                uint32_t addr = sb + (arow + mt * 16) * 128 + (((kk * 2 + a_cs) ^ a_x7) << 4);
                LDSM4(ah[mt], addr);
                LDSM4(al[mt], addr + 16384);
            }
#pragma unroll
            for (int nt2 = 0; nt2 < 4; nt2++) {
                uint32_t bh[4];
                LDSM4(bh, sb + 32768 + (brow + nt2 * 16) * 128 +
                          (((kk * 2 + b_cs) ^ b_x7) << 4));
#pragma unroll
                for (int mt = 0; mt < 4; mt++) {
                    MMAH(acc[mt][nt2 * 2],     ah[mt], bh[0], bh[1]);
                    MMAH(acc[mt][nt2 * 2 + 1], ah[mt], bh[2], bh[3]);
                    MMAH(acc[mt][nt2 * 2],     al[mt], bh[0], bh[1]);
                    MMAH(acc[mt][nt2 * 2 + 1], al[mt], bh[2], bh[3]);
                }
            }
        }
        __syncthreads();
        if (st + 3 < 16) load_stage(st + 3, buf);
        CP_COMMIT();
        buf = (buf + 1 == 3) ? 0 : buf + 1;
    }

    // fp16 epilogue: rows s*2048 + 1024 + i of g_Abf_h (1-term for gemm1)
    const int crow = lane >> 2;
    const int ccol = (lane & 3) * 2;
    __half* C = g_Abf_h + (size_t)(s * 2048 + 1024) * 1024;
#pragma unroll
    for (int mt = 0; mt < 4; mt++) {
        size_t rbase = (i0 + wm + mt * 16 + crow) * 1024 + j0 + wn + ccol;
#pragma unroll
        for (int nt = 0; nt < 8; nt++) {
            __half* p = C + rbase + nt * 8;
            *(__half2*)p            = __floats2half2_rn(acc[mt][nt][0], acc[mt][nt][1]);
            *(__half2*)(p + 8 * 1024) = __floats2half2_rn(acc[mt][nt][2], acc[mt][nt][3]);
        }
    }
}

// ---------------- gemm1: diffusion 1-term, BM=128 BN=128 BK=64, 2 CTAs/SM ----------------
#define STAGE_B1 32768
#define GEMM_DYN1 (3 * STAGE_B1)

__global__ __launch_bounds__(256, 2) void k_gemm1() {
    extern __shared__ char sm[];
    const uint32_t sbase = smem_u32(sm);
    const int tid = threadIdx.x, lane = tid & 31, wid = tid >> 5;

    const size_t i0 = (size_t)blockIdx.x * 128;
    const size_t j0 = (size_t)blockIdx.y * 128;

    const int wm = (wid & 1) * 64;
    const int wn = (wid >> 1) * 32;
    const int arow = wm + (lane & 15);
    const int a_x7 = arow & 7;
    const int a_cs = lane >> 4;
    const int brow = wn + ((lane >> 4) << 3) + (lane & 7);
    const int b_x7 = brow & 7;
    const int b_cs = (lane >> 3) & 1;

    float acc[4][4][4];
#pragma unroll
    for (int mt = 0; mt < 4; mt++)
#pragma unroll
        for (int nt = 0; nt < 4; nt++)
#pragma unroll
            for (int q = 0; q < 4; q++) acc[mt][nt][q] = 0.f;

    auto load_stage = [&](int st, int buf) {
        const int kv0 = st * 64;
        const uint32_t sb = sbase + buf * STAGE_B1;
#pragma unroll
        for (int q = 0; q < 4; q++) {
            int id = tid + 256 * q;
            int row = id >> 3, kc = id & 7;
            uint32_t sw = row * 128 + ((kc ^ (row & 7)) << 4);
            CP16(sb + sw, g_Abf_h + (i0 + row) * 1024 + kv0 + kc * 8);
        }
#pragma unroll
        for (int q = 0; q < 4; q++) {
            int id = tid + 256 * q;
            int row = id >> 3, kc = id & 7;
            uint32_t sw = row * 128 + ((kc ^ (row & 7)) << 4);
            CP16(sb + 16384 + sw, g_Xh + (j0 + row) * 1024 + kv0 + kc * 8);
        }
    };

    load_stage(0, 0); CP_COMMIT();
    load_stage(1, 1); CP_COMMIT();
    load_stage(2, 2); CP_COMMIT();

    int buf = 0;
    for (int st = 0; st < 16; ++st) {
        CP_WAIT2();
        __syncthreads();
        const uint32_t sb = sbase + buf * STAGE_B1;
#pragma unroll
        for (int kk = 0; kk < 4; kk++) {
            uint32_t ah[4][4];
#pragma unroll
            for (int mt = 0; mt < 4; mt++)
                LDSM4(ah[mt], sb + (arow + mt * 16) * 128 + (((kk * 2 + a_cs) ^ a_x7) << 4));
#pragma unroll
            for (int nt2 = 0; nt2 < 2; nt2++) {
                uint32_t bh[4];
                LDSM4(bh, sb + 16384 + (brow + nt2 * 16) * 128 +
                          (((kk * 2 + b_cs) ^ b_x7) << 4));
#pragma unroll
                for (int mt = 0; mt < 4; mt++) {
                    MMAH(acc[mt][nt2 * 2],     ah[mt], bh[0], bh[1]);
                    MMAH(acc[mt][nt2 * 2 + 1], ah[mt], bh[2], bh[3]);
                }
            }
        }
        __syncthreads();
        if (st + 3 < 16) load_stage(st + 3, buf);
        CP_COMMIT();
        buf = (buf + 1 == 3) ? 0 : buf + 1;
    }

    const int crow = lane >> 2;
    const int ccol = (lane & 3) * 2;
#pragma unroll
    for (int mt = 0; mt < 4; mt++) {
        size_t rbase = (i0 + wm + mt * 16 + crow) * MCOLS + j0 + wn + ccol;
#pragma unroll
        for (int nt = 0; nt < 4; nt++) {
            __half* p = g_yt + rbase + nt * 8;
            *(__half2*)p               = __floats2half2_rn(acc[mt][nt][0], acc[mt][nt][1]);
            *(__half2*)(p + 8 * MCOLS) = __floats2half2_rn(acc[mt][nt][2], acc[mt][nt][3]);
        }
    }
}

// ---------------- final MMA: out = Wh * H + bias; H gathered from g_Xt + g_yt ----------------
#define FIN_W    0
#define FIN_HS   (64 * PAD_E * 2)               // 29696
#define FIN_DYN  (FIN_HS + 128 * PAD_E * 2)     // 89088

__global__ __launch_bounds__(256, 2) void k_final(const float* __restrict__ bias,
                                                  float* __restrict__ out) {
    extern __shared__ char sm[];
    const uint32_t sbase = smem_u32(sm);
    const int tid = threadIdx.x, lane = tid & 31, wid = tid >> 5;
    const int b = blockIdx.y;
    const int j0 = blockIdx.x * 128;

    // group 0: W + H chunks q<14 (k 0..111)
    for (int e = tid; e < 64 * 28; e += 256) {
        int r = e / 28, q = e - r * 28;
        CP16(sbase + FIN_W + r * 464 + q * 16, g_Wh + r * CIN + q * 8);
    }
    for (int e = tid; e < 128 * 14; e += 256) {
        int r = e / 14, q = e - r * 14;
        int n = j0 + r;
        int v = n / 13, l = n - v * 13;
        const __half* src;
        if (q < 4)
            src = g_Xt + ((size_t)b * MCOLS + n) * 32 + q * 8;
        else {
            int g = (q - 4) >> 2, ch = (q - 4) & 3;
            src = g_yt + ((size_t)(g * 1024 + v)) * MCOLS + b * 416 + l * 32 + ch * 8;
        }
        CP16(sbase + FIN_HS + r * 464 + q * 16, src);
    }
    CP_COMMIT();
    // group 1: H chunks q>=14 (k 112..223)
    for (int e = tid; e < 128 * 14; e += 256) {
        int r = e / 14, q = 14 + (e - r * 14);
        int n = j0 + r;
        int v = n / 13, l = n - v * 13;
        int g = (q - 4) >> 2, ch = (q - 4) & 3;
        const __half* src = g_yt + ((size_t)(g * 1024 + v)) * MCOLS + b * 416 + l * 32 + ch * 8;
        CP16(sbase + FIN_HS + r * 464 + q * 16, src);
    }
    CP_COMMIT();

    const int wm = (wid & 1) * 32;
    const int wn = (wid >> 1) * 32;
    const int arow_l = lane & 15;
    const int a_cs = lane >> 4;
    const int brow_l = ((lane >> 4) << 3) + (lane & 7);
    const int b_cs = (lane >> 3) & 1;

    float acc[2][4][4];
#pragma unroll
    for (int mt = 0; mt < 2; mt++)
#pragma unroll
        for (int nt = 0; nt < 4; nt++)
#pragma unroll
            for (int q = 0; q < 4; q++) acc[mt][nt][q] = 0.f;

    CP_WAIT1();
    __syncthreads();

#pragma unroll
    for (int kc = 0; kc < 7; kc++) {
        uint32_t wh[2][4];
#pragma unroll
        for (int mt = 0; mt < 2; mt++)
            LDSM4(wh[mt], sbase + FIN_W + (wm + mt * 16 + arow_l) * 464 + (kc * 2 + a_cs) * 16);
#pragma unroll
        for (int nt2 = 0; nt2 < 2; nt2++) {
            uint32_t bh[4];
            LDSM4(bh, sbase + FIN_HS + (wn + nt2 * 16 + brow_l) * 464 +
                      (kc * 2 + b_cs) * 16);
#pragma unroll
            for (int mt = 0; mt < 2; mt++) {
                MMAH(acc[mt][nt2 * 2],     wh[mt], bh[0], bh[1]);
                MMAH(acc[mt][nt2 * 2 + 1], wh[mt], bh[2], bh[3]);
            }
        }
    }

    CP_WAIT0();
    __syncthreads();

#pragma unroll
    for (int kc = 7; kc < 14; kc++) {
        uint32_t wh[2][4];
#pragma unroll
        for (int mt = 0; mt < 2; mt++)
            LDSM4(wh[mt], sbase + FIN_W + (wm + mt * 16 + arow_l) * 464 + (kc * 2 + a_cs) * 16);
#pragma unroll
        for (int nt2 = 0; nt2 < 2; nt2++) {
            uint32_t bh[4];
            LDSM4(bh, sbase + FIN_HS + (wn + nt2 * 16 + brow_l) * 464 +
                      (kc * 2 + b_cs) * 16);
#pragma unroll
            for (int mt = 0; mt < 2; mt++) {
                MMAH(acc[mt][nt2 * 2],     wh[mt], bh[0], bh[1]);
                MMAH(acc[mt][nt2 * 2 + 1], wh[mt], bh[2], bh[3]);
            }
        }
    }

    const int crow = lane >> 2;
    const int ccol = (lane & 3) * 2;
#pragma unroll
    for (int mt = 0; mt < 2; mt++) {
        int o = wm + mt * 16 + crow;
        float b0 = bias[o], b1 = bias[o + 8];
        size_t r0 = (size_t)(b * 64 + o) * MCOLS + j0 + wn + ccol;
#pragma unroll
        for (int nt = 0; nt < 4; nt++) {
            float* p = out + r0 + nt * 8;
            *(float2*)p               = make_float2(acc[mt][nt][0] + b0, acc[mt][nt][1] + b0);
            *(float2*)(p + 8 * MCOLS) = make_float2(acc[mt][nt][2] + b1, acc[mt][nt][3] + b1);
        }
    }
}

// ---------------- launcher ----------------
extern "C" void kernel_launch(void* const* d_in, const int* in_sizes, int n_in,
                              void* d_out, int out_size) {
    const float* x    = (const float*)d_in[0];
    const float* A0   = (const float*)d_in[1];
    const float* A1   = (const float*)d_in[2];
    const float* A2   = (const float*)d_in[3];
    const float* W    = (const float*)d_in[4];
    const float* bias = (const float*)d_in[5];
    float* out = (float*)d_out;

    cudaFuncSetAttribute(k_gemm0, cudaFuncAttributeMaxDynamicSharedMemorySize, GEMM_DYN0);
    cudaFuncSetAttribute(k_gemm1, cudaFuncAttributeMaxDynamicSharedMemorySize, GEMM_DYN1);
    cudaFuncSetAttribute(k_final, cudaFuncAttributeMaxDynamicSharedMemorySize, FIN_DYN);

    k_stageA<<<dim3(32, 32, 3), dim3(32, 8)>>>(A0, A1, A2);
    k_stageX<<<dim3(64, 32), 256>>>(x);
    k_convW<<<56, 256>>>(W);

    k_gemm0<<<dim3(8, 4, 3), 256, GEMM_DYN0>>>();   // (A^T)^2 -> fp16 rows of g_Abf_h

    k_gemm1<<<dim3(48, 104), 256, GEMM_DYN1>>>();   // diffusion -> g_yt

    k_final<<<dim3(104, 32), 256, FIN_DYN>>>(bias, out);
}